// round 8
// baseline (speedup 1.0000x reference)
#include <cuda_runtime.h>
#include <math.h>

#define NTHREADS 256
#define BT 8
#define HD 512
#define ST 8    // column stride (floats) for column-major activations (8 rows)

typedef unsigned long long ull;

struct Smem {
    float hA[HD * ST];   // column-major: hA[c*ST + row]
    float hB[HD * ST];
    float in[16 * ST];   // column-major MLP input
    float x[BT][12];
    float fn[BT][3];
    float part[24][8];   // L3 partials
    float Im[9];
    float Iinv[9];
};

__device__ __forceinline__ float leaky(float v) { return v >= 0.f ? v : 0.01f * v; }

// packed f32x2 ops (sm_100+)
__device__ __forceinline__ ull fma2(ull a, ull b, ull c) {
    ull d;
    asm("fma.rn.f32x2 %0, %1, %2, %3;" : "=l"(d) : "l"(a), "l"(b), "l"(c));
    return d;
}
__device__ __forceinline__ ull pack2(float x) {
    ull r;
    asm("mov.b64 %0, {%1, %1};" : "=l"(r) : "f"(x));
    return r;
}
__device__ __forceinline__ float2 unpack2(ull v) {
    float2 f;
    asm("mov.b64 {%0, %1}, %2;" : "=f"(f.x), "=f"(f.y) : "l"(v));
    return f;
}

// 512 -> 512 layer, col-major activations (8 rows), 4-deep W pipeline.
// Thread tx in [0,256): all 8 rows, cols {2tx, 2tx+1}.
// Per k: 1x LDG.64 (W pair, prefetched), 2x pack, 2x LDS.128, 8x FFMA2.
__device__ __forceinline__ void layer512(const float* __restrict__ si,
                                         float* __restrict__ so,
                                         const float* __restrict__ W,
                                         const float* __restrict__ bv,
                                         int tx) {
    const int c0 = tx * 2;
    ull acc[4][2];
#pragma unroll
    for (int p = 0; p < 4; p++) { acc[p][0] = 0ULL; acc[p][1] = 0ULL; }

    const float2* W2 = reinterpret_cast<const float2*>(W);   // [k][256] float2
    float2 wc[4], wn[4];
#pragma unroll
    for (int u = 0; u < 4; u++) wc[u] = W2[u * 256 + tx];

    for (int k0 = 0; k0 < HD; k0 += 4) {
        // batch activation LDS for this window (8 outstanding LDS.128)
        ulonglong2 aA[4], aB[4];
#pragma unroll
        for (int u = 0; u < 4; u++) {
            const float* a = si + (k0 + u) * ST;
            aA[u] = *reinterpret_cast<const ulonglong2*>(a);
            aB[u] = *reinterpret_cast<const ulonglong2*>(a + 4);
        }
        // prefetch next W window
        const bool pf = (k0 + 4) < HD;
        const float2* wpn = W2 + (k0 + 4) * 256 + tx;
#pragma unroll
        for (int u = 0; u < 4; u++)
            if (pf) wn[u] = wpn[u * 256];
        // hoisted packs + FMA body
#pragma unroll
        for (int u = 0; u < 4; u++) {
            ull w0 = pack2(wc[u].x);
            ull w1 = pack2(wc[u].y);
            acc[0][0] = fma2(aA[u].x, w0, acc[0][0]);
            acc[0][1] = fma2(aA[u].x, w1, acc[0][1]);
            acc[1][0] = fma2(aA[u].y, w0, acc[1][0]);
            acc[1][1] = fma2(aA[u].y, w1, acc[1][1]);
            acc[2][0] = fma2(aB[u].x, w0, acc[2][0]);
            acc[2][1] = fma2(aB[u].x, w1, acc[2][1]);
            acc[3][0] = fma2(aB[u].y, w0, acc[3][0]);
            acc[3][1] = fma2(aB[u].y, w1, acc[3][1]);
        }
#pragma unroll
        for (int u = 0; u < 4; u++) wc[u] = wn[u];
    }

    const float2 bb = *reinterpret_cast<const float2*>(bv + c0);
#pragma unroll
    for (int c = 0; c < 2; c++) {
        const float b = (c == 0) ? bb.x : bb.y;
        float2 v0 = unpack2(acc[0][c]);
        float2 v1 = unpack2(acc[1][c]);
        float2 v2 = unpack2(acc[2][c]);
        float2 v3 = unpack2(acc[3][c]);
        float4 o0, o1;
        o0.x = leaky(v0.x + b); o0.y = leaky(v0.y + b);
        o0.z = leaky(v1.x + b); o0.w = leaky(v1.y + b);
        o1.x = leaky(v2.x + b); o1.y = leaky(v2.y + b);
        o1.z = leaky(v3.x + b); o1.w = leaky(v3.y + b);
        float* op = so + (c0 + c) * ST;
        *reinterpret_cast<float4*>(op) = o0;
        *reinterpret_cast<float4*>(op + 4) = o1;
    }
}

// 16 -> 512 layer (same mapping, K=16)
__device__ __forceinline__ void layer16(const float* __restrict__ si,
                                        float* __restrict__ so,
                                        const float* __restrict__ W,
                                        const float* __restrict__ bv,
                                        int tx) {
    const int c0 = tx * 2;
    ull acc[4][2];
#pragma unroll
    for (int p = 0; p < 4; p++) { acc[p][0] = 0ULL; acc[p][1] = 0ULL; }

    const float2* W2 = reinterpret_cast<const float2*>(W);
#pragma unroll
    for (int k = 0; k < 16; k++) {
        float2 w = W2[k * 256 + tx];
        ull w0 = pack2(w.x);
        ull w1 = pack2(w.y);
        const float* a = si + k * ST;
        ulonglong2 aA = *reinterpret_cast<const ulonglong2*>(a);
        ulonglong2 aB = *reinterpret_cast<const ulonglong2*>(a + 4);
        acc[0][0] = fma2(aA.x, w0, acc[0][0]);
        acc[0][1] = fma2(aA.x, w1, acc[0][1]);
        acc[1][0] = fma2(aA.y, w0, acc[1][0]);
        acc[1][1] = fma2(aA.y, w1, acc[1][1]);
        acc[2][0] = fma2(aB.x, w0, acc[2][0]);
        acc[2][1] = fma2(aB.x, w1, acc[2][1]);
        acc[3][0] = fma2(aB.y, w0, acc[3][0]);
        acc[3][1] = fma2(aB.y, w1, acc[3][1]);
    }

    const float2 bb = *reinterpret_cast<const float2*>(bv + c0);
#pragma unroll
    for (int c = 0; c < 2; c++) {
        const float b = (c == 0) ? bb.x : bb.y;
        float2 v0 = unpack2(acc[0][c]);
        float2 v1 = unpack2(acc[1][c]);
        float2 v2 = unpack2(acc[2][c]);
        float2 v3 = unpack2(acc[3][c]);
        float4 o0, o1;
        o0.x = leaky(v0.x + b); o0.y = leaky(v0.y + b);
        o0.z = leaky(v1.x + b); o0.w = leaky(v1.y + b);
        o1.x = leaky(v2.x + b); o1.y = leaky(v2.y + b);
        o1.z = leaky(v3.x + b); o1.w = leaky(v3.y + b);
        float* op = so + (c0 + c) * ST;
        *reinterpret_cast<float4*>(op) = o0;
        *reinterpret_cast<float4*>(op + 4) = o1;
    }
}

// Rigid-body derivatives, M (moments) == 0.
__device__ __forceinline__ void derivs(const float x[12], float F0, float F1, float F2,
                                       const float Im[9], const float Iv[9], float dx[12]) {
    float V0 = x[3], V1 = x[4], V2 = x[5];
    float phi = x[6], th = x[7], ps = x[8];
    float w0 = x[9], w1 = x[10], w2 = x[11];
    float cph = cosf(phi), sph = sinf(phi);
    float cth = cosf(th), sth = sinf(th);
    float cps = cosf(ps), sps = sinf(ps);

    dx[0] = (cth * cps) * V0 + (sph * sth * cps - cph * sps) * V1 + (cph * sth * cps + sph * sps) * V2;
    dx[1] = (cth * sps) * V0 + (sph * sth * sps + cph * cps) * V1 + (cph * sth * sps - sph * cps) * V2;
    dx[2] = (-sth) * V0 + (sph * cth) * V1 + (cph * cth) * V2;

    dx[3] = F0 / 1.5f - (w1 * V2 - w2 * V1);
    dx[4] = F1 / 1.5f - (w2 * V0 - w0 * V2);
    dx[5] = F2 / 1.5f - (w0 * V1 - w1 * V0);

    float tth = tanf(th);
    float cthc = fmaxf(cth, 1e-6f);
    float ic = 1.0f / cthc;
    dx[6] = w0 + sph * tth * w1 + cph * tth * w2;
    dx[7] = cph * w1 - sph * w2;
    dx[8] = (sph * ic) * w1 + (cph * ic) * w2;

    float Iw0 = Im[0] * w0 + Im[1] * w1 + Im[2] * w2;
    float Iw1 = Im[3] * w0 + Im[4] * w1 + Im[5] * w2;
    float Iw2 = Im[6] * w0 + Im[7] * w1 + Im[8] * w2;
    float c0 = w1 * Iw2 - w2 * Iw1;
    float c1 = w2 * Iw0 - w0 * Iw2;
    float c2 = w0 * Iw1 - w1 * Iw0;
    dx[9]  = -(Iv[0] * c0 + Iv[1] * c1 + Iv[2] * c2);
    dx[10] = -(Iv[3] * c0 + Iv[4] * c1 + Iv[5] * c2);
    dx[11] = -(Iv[6] * c0 + Iv[7] * c1 + Iv[8] * c2);
}

extern "C" __global__ void __launch_bounds__(NTHREADS, 2)
wm_rollout(const float* __restrict__ x_t, const float* __restrict__ act,
           const float* __restrict__ Imat_g,
           const float* __restrict__ W0, const float* __restrict__ b0,
           const float* __restrict__ W1, const float* __restrict__ b1,
           const float* __restrict__ W2, const float* __restrict__ b2,
           const float* __restrict__ W3, const float* __restrict__ b3,
           const int* __restrict__ seqp, float* __restrict__ out, int Bn) {
    extern __shared__ char smc[];
    Smem& S = *reinterpret_cast<Smem*>(smc);
    const int tid = threadIdx.x;
    const int tx = tid;            // 0..255

    const int T = seqp[0];
    const int steps = T - 1;
    float* outF = out;                                   // [B, 6, T-1]
    float* outX = out + (size_t)Bn * 6 * steps;          // [B, 12, T]

    if (tid == 0) {
        float a = Imat_g[0], b = Imat_g[1], c = Imat_g[2];
        float d = Imat_g[3], e = Imat_g[4], f = Imat_g[5];
        float g = Imat_g[6], h = Imat_g[7], i = Imat_g[8];
        float A = e * i - f * h;
        float Bc = -(d * i - f * g);
        float C = d * h - e * g;
        float det = a * A + b * Bc + c * C;
        float id = 1.0f / det;
        S.Iinv[0] = A * id;            S.Iinv[1] = (c * h - b * i) * id;  S.Iinv[2] = (b * f - c * e) * id;
        S.Iinv[3] = Bc * id;           S.Iinv[4] = (a * i - c * g) * id;  S.Iinv[5] = (c * d - a * f) * id;
        S.Iinv[6] = C * id;            S.Iinv[7] = (b * g - a * h) * id;  S.Iinv[8] = (a * e - b * d) * id;
#pragma unroll
        for (int k = 0; k < 9; k++) S.Im[k] = Imat_g[k];
    }

    if (tid < BT) {
        const int row = tid;
        const size_t bidx = (size_t)blockIdx.x * BT + row;
#pragma unroll
        for (int s = 0; s < 12; s++) {
            float v = x_t[bidx * 12 + s];
            S.x[row][s] = v;
            outX[bidx * 12 * T + (size_t)s * T + 0] = v;
        }
    }
    __syncthreads();

    // per-thread copies of I and I^-1 for RK4 threads
    float ImR[9], IvR[9];
    if (tid < BT) {
#pragma unroll
        for (int k = 0; k < 9; k++) { ImR[k] = S.Im[k]; IvR[k] = S.Iinv[k]; }
    }

    for (int t = 0; t < steps; t++) {
        // ---- build MLP input, column-major: in[k*ST + row] ----
        if (tid < BT) {
            const int row = tid;
            const size_t bidx = (size_t)blockIdx.x * BT + row;
            S.in[0 * ST + row] = S.x[row][0] * 1.2732395447351628f;
            S.in[1 * ST + row] = S.x[row][1] * 0.5f;
            S.in[2 * ST + row] = S.x[row][2] * 1.2732395447351628f;
            S.in[3 * ST + row] = S.x[row][3] * 0.1f;
            S.in[4 * ST + row] = S.x[row][4] * 0.016666666666666666f;
            S.in[5 * ST + row] = S.x[row][5] * 0.016666666666666666f;
#pragma unroll
            for (int s = 6; s < 12; s++) S.in[s * ST + row] = 0.f;
#pragma unroll
            for (int a = 0; a < 4; a++)
                S.in[(12 + a) * ST + row] = (act[(bidx * 4 + a) * T + (t + 1)] - 1500.0f) / 500.0f;
        }
        __syncthreads();

        layer16(S.in, S.hA, W0, b0, tx);
        __syncthreads();
        layer512(S.hA, S.hB, W1, b1, tx);
        __syncthreads();
        layer512(S.hB, S.hA, W2, b2, tx);
        __syncthreads();

        // ---- layer 3 over 192 threads: 24 dots x 8 k-partials of 64 ----
        {
            const int o = tid >> 3;          // 0..31 (use 0..23)
            const int h = tid & 7;           // k-partial
            if (o < 24) {
                const int row = o / 3;
                const int cc = o - row * 3;
                const float* hp = S.hA + row;
                const float* wp = W3 + cc;
                float s = 0.f;
                const int kb = h * 64;
#pragma unroll 8
                for (int k = 0; k < 64; k++)
                    s = fmaf(hp[(kb + k) * ST], wp[(kb + k) * 6], s);
                S.part[o][h] = s;
            }
        }
        __syncthreads();
        if (tid < 24) {
            const int row = tid / 3;
            const int cc = tid - row * 3;
            const float* pp = S.part[tid];
            float s = ((pp[0] + pp[1]) + (pp[2] + pp[3])) + ((pp[4] + pp[5]) + (pp[6] + pp[7]));
            S.fn[row][cc] = s + b3[cc];
        }
        __syncthreads();

        // ---- forces + RK4 + outputs ----
        if (tid < BT) {
            const int row = tid;
            const size_t bidx = (size_t)blockIdx.x * BT + row;
            const float F0 = S.fn[row][0] - 0.5f;
            const float F1 = S.fn[row][1] * (-0.4f) - 10.0f;
            const float F2 = S.fn[row][2] * 0.2f - 0.1f;

            float* fo = outF + bidx * 6 * steps + t;
            fo[0 * steps] = F0;
            fo[1 * steps] = F1;
            fo[2 * steps] = F2;
            fo[3 * steps] = 0.f;
            fo[4 * steps] = 0.f;
            fo[5 * steps] = 0.f;

            float xx[12];
#pragma unroll
            for (int s = 0; s < 12; s++) xx[s] = S.x[row][s];
            float k1[12], k2[12], k3[12], k4[12], tm[12];
            derivs(xx, F0, F1, F2, ImR, IvR, k1);
#pragma unroll
            for (int s = 0; s < 12; s++) tm[s] = xx[s] + 0.005f * k1[s];
            derivs(tm, F0, F1, F2, ImR, IvR, k2);
#pragma unroll
            for (int s = 0; s < 12; s++) tm[s] = xx[s] + 0.005f * k2[s];
            derivs(tm, F0, F1, F2, ImR, IvR, k3);
#pragma unroll
            for (int s = 0; s < 12; s++) tm[s] = xx[s] + 0.01f * k3[s];
            derivs(tm, F0, F1, F2, ImR, IvR, k4);
            const float w6 = (float)(0.01 / 6.0);
#pragma unroll
            for (int s = 0; s < 12; s++)
                xx[s] = xx[s] + w6 * (k1[s] + 2.f * k2[s] + 2.f * k3[s] + k4[s]);

            float* xo = outX + bidx * 12 * T + (t + 1);
#pragma unroll
            for (int s = 0; s < 12; s++) {
                S.x[row][s] = xx[s];
                xo[(size_t)s * T] = xx[s];
            }
        }
        __syncthreads();
    }
}

extern "C" void kernel_launch(void* const* d_in, const int* in_sizes, int n_in,
                              void* d_out, int out_size) {
    // metadata order follows setup_inputs() dict insertion order:
    // 0: x_t, 1: act_inps, 2: I_mat, 3: seq_len, 4..11: W0,b0,W1,b1,W2,b2,W3,b3
    const float* x_t = (const float*)d_in[0];
    const float* act = (const float*)d_in[1];
    const float* Im  = (const float*)d_in[2];
    const int* seqp  = (const int*)d_in[3];
    const float* W0  = (const float*)d_in[4];
    const float* b0  = (const float*)d_in[5];
    const float* W1  = (const float*)d_in[6];
    const float* b1  = (const float*)d_in[7];
    const float* W2  = (const float*)d_in[8];
    const float* b2  = (const float*)d_in[9];
    const float* W3  = (const float*)d_in[10];
    const float* b3  = (const float*)d_in[11];

    const int Bn = in_sizes[0] / 12;
    const int grid = Bn / BT;
    const size_t sm = sizeof(Smem);

    cudaFuncSetAttribute(wm_rollout, cudaFuncAttributeMaxDynamicSharedMemorySize, (int)sm);
    wm_rollout<<<grid, NTHREADS, sm>>>(x_t, act, Im, W0, b0, W1, b1, W2, b2, W3, b3,
                                       seqp, (float*)d_out, Bn);
}

// round 9
// speedup vs baseline: 1.0009x; 1.0009x over previous
#include <cuda_runtime.h>
#include <math.h>

#define NTHREADS 256
#define BT 8
#define HD 512
#define ST 8    // column stride (floats) for column-major activations (8 rows)

typedef unsigned long long ull;

struct Smem {
    float hA[HD * ST];   // column-major: hA[c*ST + row]
    float hB[HD * ST];
    float in[16 * ST];   // column-major MLP input
    float x[BT][12];
    float fn[BT][3];
    float part[24][8];   // L3 partials
    float Im[9];
    float Iinv[9];
};

__device__ __forceinline__ float leaky(float v) { return v >= 0.f ? v : 0.01f * v; }

// packed f32x2 ops (sm_100+)
__device__ __forceinline__ ull fma2(ull a, ull b, ull c) {
    ull d;
    asm("fma.rn.f32x2 %0, %1, %2, %3;" : "=l"(d) : "l"(a), "l"(b), "l"(c));
    return d;
}
__device__ __forceinline__ ull pack2(float x) {
    ull r;
    asm("mov.b64 %0, {%1, %1};" : "=l"(r) : "f"(x));
    return r;
}
__device__ __forceinline__ float2 unpack2(ull v) {
    float2 f;
    asm("mov.b64 {%0, %1}, %2;" : "=f"(f.x), "=f"(f.y) : "l"(v));
    return f;
}

// 512 -> 512 layer, col-major activations (8 rows), 4-deep W pipeline.
// Thread tx in [0,256): all 8 rows, cols {2tx, 2tx+1}.
// Per k: 1x LDG.64 (W pair, prefetched), 2x pack, 2x LDS.128, 8x FFMA2.
__device__ __forceinline__ void layer512(const float* __restrict__ si,
                                         float* __restrict__ so,
                                         const float* __restrict__ W,
                                         const float* __restrict__ bv,
                                         int tx) {
    const int c0 = tx * 2;
    ull acc[4][2];
#pragma unroll
    for (int p = 0; p < 4; p++) { acc[p][0] = 0ULL; acc[p][1] = 0ULL; }

    const float2* W2 = reinterpret_cast<const float2*>(W);   // [k][256] float2
    float2 wc[4], wn[4];
#pragma unroll
    for (int u = 0; u < 4; u++) wc[u] = W2[u * 256 + tx];

    for (int k0 = 0; k0 < HD; k0 += 4) {
        // batch activation LDS for this window (8 outstanding LDS.128)
        ulonglong2 aA[4], aB[4];
#pragma unroll
        for (int u = 0; u < 4; u++) {
            const float* a = si + (k0 + u) * ST;
            aA[u] = *reinterpret_cast<const ulonglong2*>(a);
            aB[u] = *reinterpret_cast<const ulonglong2*>(a + 4);
        }
        // prefetch next W window
        const bool pf = (k0 + 4) < HD;
        const float2* wpn = W2 + (k0 + 4) * 256 + tx;
#pragma unroll
        for (int u = 0; u < 4; u++)
            if (pf) wn[u] = wpn[u * 256];
        // hoisted packs + FMA body
#pragma unroll
        for (int u = 0; u < 4; u++) {
            ull w0 = pack2(wc[u].x);
            ull w1 = pack2(wc[u].y);
            acc[0][0] = fma2(aA[u].x, w0, acc[0][0]);
            acc[0][1] = fma2(aA[u].x, w1, acc[0][1]);
            acc[1][0] = fma2(aA[u].y, w0, acc[1][0]);
            acc[1][1] = fma2(aA[u].y, w1, acc[1][1]);
            acc[2][0] = fma2(aB[u].x, w0, acc[2][0]);
            acc[2][1] = fma2(aB[u].x, w1, acc[2][1]);
            acc[3][0] = fma2(aB[u].y, w0, acc[3][0]);
            acc[3][1] = fma2(aB[u].y, w1, acc[3][1]);
        }
#pragma unroll
        for (int u = 0; u < 4; u++) wc[u] = wn[u];
    }

    const float2 bb = *reinterpret_cast<const float2*>(bv + c0);
#pragma unroll
    for (int c = 0; c < 2; c++) {
        const float b = (c == 0) ? bb.x : bb.y;
        float2 v0 = unpack2(acc[0][c]);
        float2 v1 = unpack2(acc[1][c]);
        float2 v2 = unpack2(acc[2][c]);
        float2 v3 = unpack2(acc[3][c]);
        float4 o0, o1;
        o0.x = leaky(v0.x + b); o0.y = leaky(v0.y + b);
        o0.z = leaky(v1.x + b); o0.w = leaky(v1.y + b);
        o1.x = leaky(v2.x + b); o1.y = leaky(v2.y + b);
        o1.z = leaky(v3.x + b); o1.w = leaky(v3.y + b);
        float* op = so + (c0 + c) * ST;
        *reinterpret_cast<float4*>(op) = o0;
        *reinterpret_cast<float4*>(op + 4) = o1;
    }
}

// 16 -> 512 layer (same mapping, K=16)
__device__ __forceinline__ void layer16(const float* __restrict__ si,
                                        float* __restrict__ so,
                                        const float* __restrict__ W,
                                        const float* __restrict__ bv,
                                        int tx) {
    const int c0 = tx * 2;
    ull acc[4][2];
#pragma unroll
    for (int p = 0; p < 4; p++) { acc[p][0] = 0ULL; acc[p][1] = 0ULL; }

    const float2* W2 = reinterpret_cast<const float2*>(W);
#pragma unroll
    for (int k = 0; k < 16; k++) {
        float2 w = W2[k * 256 + tx];
        ull w0 = pack2(w.x);
        ull w1 = pack2(w.y);
        const float* a = si + k * ST;
        ulonglong2 aA = *reinterpret_cast<const ulonglong2*>(a);
        ulonglong2 aB = *reinterpret_cast<const ulonglong2*>(a + 4);
        acc[0][0] = fma2(aA.x, w0, acc[0][0]);
        acc[0][1] = fma2(aA.x, w1, acc[0][1]);
        acc[1][0] = fma2(aA.y, w0, acc[1][0]);
        acc[1][1] = fma2(aA.y, w1, acc[1][1]);
        acc[2][0] = fma2(aB.x, w0, acc[2][0]);
        acc[2][1] = fma2(aB.x, w1, acc[2][1]);
        acc[3][0] = fma2(aB.y, w0, acc[3][0]);
        acc[3][1] = fma2(aB.y, w1, acc[3][1]);
    }

    const float2 bb = *reinterpret_cast<const float2*>(bv + c0);
#pragma unroll
    for (int c = 0; c < 2; c++) {
        const float b = (c == 0) ? bb.x : bb.y;
        float2 v0 = unpack2(acc[0][c]);
        float2 v1 = unpack2(acc[1][c]);
        float2 v2 = unpack2(acc[2][c]);
        float2 v3 = unpack2(acc[3][c]);
        float4 o0, o1;
        o0.x = leaky(v0.x + b); o0.y = leaky(v0.y + b);
        o0.z = leaky(v1.x + b); o0.w = leaky(v1.y + b);
        o1.x = leaky(v2.x + b); o1.y = leaky(v2.y + b);
        o1.z = leaky(v3.x + b); o1.w = leaky(v3.y + b);
        float* op = so + (c0 + c) * ST;
        *reinterpret_cast<float4*>(op) = o0;
        *reinterpret_cast<float4*>(op + 4) = o1;
    }
}

// Rigid-body derivatives, M (moments) == 0.
__device__ __forceinline__ void derivs(const float x[12], float F0, float F1, float F2,
                                       const float Im[9], const float Iv[9], float dx[12]) {
    float V0 = x[3], V1 = x[4], V2 = x[5];
    float phi = x[6], th = x[7], ps = x[8];
    float w0 = x[9], w1 = x[10], w2 = x[11];
    float cph = cosf(phi), sph = sinf(phi);
    float cth = cosf(th), sth = sinf(th);
    float cps = cosf(ps), sps = sinf(ps);

    dx[0] = (cth * cps) * V0 + (sph * sth * cps - cph * sps) * V1 + (cph * sth * cps + sph * sps) * V2;
    dx[1] = (cth * sps) * V0 + (sph * sth * sps + cph * cps) * V1 + (cph * sth * sps - sph * cps) * V2;
    dx[2] = (-sth) * V0 + (sph * cth) * V1 + (cph * cth) * V2;

    dx[3] = F0 / 1.5f - (w1 * V2 - w2 * V1);
    dx[4] = F1 / 1.5f - (w2 * V0 - w0 * V2);
    dx[5] = F2 / 1.5f - (w0 * V1 - w1 * V0);

    float tth = tanf(th);
    float cthc = fmaxf(cth, 1e-6f);
    float ic = 1.0f / cthc;
    dx[6] = w0 + sph * tth * w1 + cph * tth * w2;
    dx[7] = cph * w1 - sph * w2;
    dx[8] = (sph * ic) * w1 + (cph * ic) * w2;

    float Iw0 = Im[0] * w0 + Im[1] * w1 + Im[2] * w2;
    float Iw1 = Im[3] * w0 + Im[4] * w1 + Im[5] * w2;
    float Iw2 = Im[6] * w0 + Im[7] * w1 + Im[8] * w2;
    float c0 = w1 * Iw2 - w2 * Iw1;
    float c1 = w2 * Iw0 - w0 * Iw2;
    float c2 = w0 * Iw1 - w1 * Iw0;
    dx[9]  = -(Iv[0] * c0 + Iv[1] * c1 + Iv[2] * c2);
    dx[10] = -(Iv[3] * c0 + Iv[4] * c1 + Iv[5] * c2);
    dx[11] = -(Iv[6] * c0 + Iv[7] * c1 + Iv[8] * c2);
}

extern "C" __global__ void __launch_bounds__(NTHREADS, 2)
wm_rollout(const float* __restrict__ x_t, const float* __restrict__ act,
           const float* __restrict__ Imat_g,
           const float* __restrict__ W0, const float* __restrict__ b0,
           const float* __restrict__ W1, const float* __restrict__ b1,
           const float* __restrict__ W2, const float* __restrict__ b2,
           const float* __restrict__ W3, const float* __restrict__ b3,
           const int* __restrict__ seqp, float* __restrict__ out, int Bn) {
    extern __shared__ char smc[];
    Smem& S = *reinterpret_cast<Smem*>(smc);
    const int tid = threadIdx.x;
    const int tx = tid;            // 0..255

    const int T = seqp[0];
    const int steps = T - 1;
    float* outF = out;                                   // [B, 6, T-1]
    float* outX = out + (size_t)Bn * 6 * steps;          // [B, 12, T]

    if (tid == 0) {
        float a = Imat_g[0], b = Imat_g[1], c = Imat_g[2];
        float d = Imat_g[3], e = Imat_g[4], f = Imat_g[5];
        float g = Imat_g[6], h = Imat_g[7], i = Imat_g[8];
        float A = e * i - f * h;
        float Bc = -(d * i - f * g);
        float C = d * h - e * g;
        float det = a * A + b * Bc + c * C;
        float id = 1.0f / det;
        S.Iinv[0] = A * id;            S.Iinv[1] = (c * h - b * i) * id;  S.Iinv[2] = (b * f - c * e) * id;
        S.Iinv[3] = Bc * id;           S.Iinv[4] = (a * i - c * g) * id;  S.Iinv[5] = (c * d - a * f) * id;
        S.Iinv[6] = C * id;            S.Iinv[7] = (b * g - a * h) * id;  S.Iinv[8] = (a * e - b * d) * id;
#pragma unroll
        for (int k = 0; k < 9; k++) S.Im[k] = Imat_g[k];
    }

    if (tid < BT) {
        const int row = tid;
        const size_t bidx = (size_t)blockIdx.x * BT + row;
#pragma unroll
        for (int s = 0; s < 12; s++) {
            float v = x_t[bidx * 12 + s];
            S.x[row][s] = v;
            outX[bidx * 12 * T + (size_t)s * T + 0] = v;
        }
    }
    __syncthreads();

    // per-thread copies of I and I^-1 for RK4 threads
    float ImR[9], IvR[9];
    if (tid < BT) {
#pragma unroll
        for (int k = 0; k < 9; k++) { ImR[k] = S.Im[k]; IvR[k] = S.Iinv[k]; }
    }

    for (int t = 0; t < steps; t++) {
        // ---- build MLP input, column-major: in[k*ST + row] ----
        if (tid < BT) {
            const int row = tid;
            const size_t bidx = (size_t)blockIdx.x * BT + row;
            S.in[0 * ST + row] = S.x[row][0] * 1.2732395447351628f;
            S.in[1 * ST + row] = S.x[row][1] * 0.5f;
            S.in[2 * ST + row] = S.x[row][2] * 1.2732395447351628f;
            S.in[3 * ST + row] = S.x[row][3] * 0.1f;
            S.in[4 * ST + row] = S.x[row][4] * 0.016666666666666666f;
            S.in[5 * ST + row] = S.x[row][5] * 0.016666666666666666f;
#pragma unroll
            for (int s = 6; s < 12; s++) S.in[s * ST + row] = 0.f;
#pragma unroll
            for (int a = 0; a < 4; a++)
                S.in[(12 + a) * ST + row] = (act[(bidx * 4 + a) * T + (t + 1)] - 1500.0f) / 500.0f;
        }
        __syncthreads();

        layer16(S.in, S.hA, W0, b0, tx);
        __syncthreads();
        layer512(S.hA, S.hB, W1, b1, tx);
        __syncthreads();
        layer512(S.hB, S.hA, W2, b2, tx);
        __syncthreads();

        // ---- layer 3 over 192 threads: 24 dots x 8 k-partials of 64 ----
        {
            const int o = tid >> 3;          // 0..31 (use 0..23)
            const int h = tid & 7;           // k-partial
            if (o < 24) {
                const int row = o / 3;
                const int cc = o - row * 3;
                const float* hp = S.hA + row;
                const float* wp = W3 + cc;
                float s = 0.f;
                const int kb = h * 64;
#pragma unroll 8
                for (int k = 0; k < 64; k++)
                    s = fmaf(hp[(kb + k) * ST], wp[(kb + k) * 6], s);
                S.part[o][h] = s;
            }
        }
        __syncthreads();
        if (tid < 24) {
            const int row = tid / 3;
            const int cc = tid - row * 3;
            const float* pp = S.part[tid];
            float s = ((pp[0] + pp[1]) + (pp[2] + pp[3])) + ((pp[4] + pp[5]) + (pp[6] + pp[7]));
            S.fn[row][cc] = s + b3[cc];
        }
        __syncthreads();

        // ---- forces + RK4 + outputs ----
        if (tid < BT) {
            const int row = tid;
            const size_t bidx = (size_t)blockIdx.x * BT + row;
            const float F0 = S.fn[row][0] - 0.5f;
            const float F1 = S.fn[row][1] * (-0.4f) - 10.0f;
            const float F2 = S.fn[row][2] * 0.2f - 0.1f;

            float* fo = outF + bidx * 6 * steps + t;
            fo[0 * steps] = F0;
            fo[1 * steps] = F1;
            fo[2 * steps] = F2;
            fo[3 * steps] = 0.f;
            fo[4 * steps] = 0.f;
            fo[5 * steps] = 0.f;

            float xx[12];
#pragma unroll
            for (int s = 0; s < 12; s++) xx[s] = S.x[row][s];
            float k1[12], k2[12], k3[12], k4[12], tm[12];
            derivs(xx, F0, F1, F2, ImR, IvR, k1);
#pragma unroll
            for (int s = 0; s < 12; s++) tm[s] = xx[s] + 0.005f * k1[s];
            derivs(tm, F0, F1, F2, ImR, IvR, k2);
#pragma unroll
            for (int s = 0; s < 12; s++) tm[s] = xx[s] + 0.005f * k2[s];
            derivs(tm, F0, F1, F2, ImR, IvR, k3);
#pragma unroll
            for (int s = 0; s < 12; s++) tm[s] = xx[s] + 0.01f * k3[s];
            derivs(tm, F0, F1, F2, ImR, IvR, k4);
            const float w6 = (float)(0.01 / 6.0);
#pragma unroll
            for (int s = 0; s < 12; s++)
                xx[s] = xx[s] + w6 * (k1[s] + 2.f * k2[s] + 2.f * k3[s] + k4[s]);

            float* xo = outX + bidx * 12 * T + (t + 1);
#pragma unroll
            for (int s = 0; s < 12; s++) {
                S.x[row][s] = xx[s];
                xo[(size_t)s * T] = xx[s];
            }
        }
        __syncthreads();
    }
}

extern "C" void kernel_launch(void* const* d_in, const int* in_sizes, int n_in,
                              void* d_out, int out_size) {
    // metadata order follows setup_inputs() dict insertion order:
    // 0: x_t, 1: act_inps, 2: I_mat, 3: seq_len, 4..11: W0,b0,W1,b1,W2,b2,W3,b3
    const float* x_t = (const float*)d_in[0];
    const float* act = (const float*)d_in[1];
    const float* Im  = (const float*)d_in[2];
    const int* seqp  = (const int*)d_in[3];
    const float* W0  = (const float*)d_in[4];
    const float* b0  = (const float*)d_in[5];
    const float* W1  = (const float*)d_in[6];
    const float* b1  = (const float*)d_in[7];
    const float* W2  = (const float*)d_in[8];
    const float* b2  = (const float*)d_in[9];
    const float* W3  = (const float*)d_in[10];
    const float* b3  = (const float*)d_in[11];

    const int Bn = in_sizes[0] / 12;
    const int grid = Bn / BT;
    const size_t sm = sizeof(Smem);

    cudaFuncSetAttribute(wm_rollout, cudaFuncAttributeMaxDynamicSharedMemorySize, (int)sm);
    wm_rollout<<<grid, NTHREADS, sm>>>(x_t, act, Im, W0, b0, W1, b1, W2, b2, W3, b3,
                                       seqp, (float*)d_out, Bn);
}

// round 11
// speedup vs baseline: 1.4937x; 1.4924x over previous
#include <cuda_runtime.h>
#include <cuda_bf16.h>
#include <math.h>
#include <stdint.h>

#define NTH 512
#define BT 16
#define HD 512
#define AST 520   // activation row stride in elems (1040B -> bank offset 4 mod 32, conflict-free frags)

typedef unsigned long long ull;

// Fragment-packed weights: uint4 per (layer, warp, kstep, ntile, lane)
// idx = ((l*16 + w)*32 + ks)*128 + nt*32 + lane ; payload = {bh0, bh1, bl0, bl1}
__device__ __align__(16) uint4 g_wt[2 * 16 * 32 * 4 * 32];

struct Smem {
    __nv_bfloat16 Ah[BT * AST];   // activations hi: [row][k]
    __nv_bfloat16 Al[BT * AST];   // lo
    float in[16 * BT];            // L0 input col-major [k][row]
    float x[BT][12];
    float fn[BT][3];
    float part[48][8];
    float Im[9], Iinv[9];
};

__device__ __forceinline__ float leaky(float v) { return v >= 0.f ? v : 0.01f * v; }
__device__ __forceinline__ ull fma2(ull a, ull b, ull c) {
    ull d;
    asm("fma.rn.f32x2 %0, %1, %2, %3;" : "=l"(d) : "l"(a), "l"(b), "l"(c));
    return d;
}
__device__ __forceinline__ ull pack2(float x) {
    ull r;
    asm("mov.b64 %0, {%1, %1};" : "=l"(r) : "f"(x));
    return r;
}
__device__ __forceinline__ float2 unpack2(ull v) {
    float2 f;
    asm("mov.b64 {%0, %1}, %2;" : "=f"(f.x), "=f"(f.y) : "l"(v));
    return f;
}

// mma.m16n8k16 row.col bf16 -> f32 accum (portable HMMA, sm_80+)
__device__ __forceinline__ void mma16816(float d[4], unsigned a0, unsigned a1, unsigned a2,
                                         unsigned a3, unsigned b0, unsigned b1) {
    asm volatile(
        "mma.sync.aligned.m16n8k16.row.col.f32.bf16.bf16.f32 "
        "{%0,%1,%2,%3}, {%4,%5,%6,%7}, {%8,%9}, {%0,%1,%2,%3};"
        : "+f"(d[0]), "+f"(d[1]), "+f"(d[2]), "+f"(d[3])
        : "r"(a0), "r"(a1), "r"(a2), "r"(a3), "r"(b0), "r"(b1));
}

__device__ __forceinline__ unsigned bf16pack(float lo_elem, float hi_elem) {
    // returns b32 with lo_elem in bits[0:16), hi_elem in [16:32)
    unsigned short s0 = __bfloat16_as_ushort(__float2bfloat16_rn(lo_elem));
    unsigned short s1 = __bfloat16_as_ushort(__float2bfloat16_rn(hi_elem));
    return ((unsigned)s1 << 16) | s0;
}

// ---------------- prep: pack W1/W2 into fragment order, bf16 hi/lo ----------------
extern "C" __global__ void wm_prep(const float* __restrict__ W1, const float* __restrict__ W2) {
    int idx = blockIdx.x * blockDim.x + threadIdx.x;   // 131072 total
    int lane = idx & 31;
    int nt = (idx >> 5) & 3;
    int ks = (idx >> 7) & 31;
    int w = (idx >> 12) & 15;
    int l = idx >> 16;
    int g = lane >> 2, tig = lane & 3;
    int k0 = ks * 16 + tig * 2;
    int n = (w * 4 + nt) * 8 + g;
    const float* W = l ? W2 : W1;
    float v00 = W[(k0 + 0) * 512 + n];
    float v01 = W[(k0 + 1) * 512 + n];
    float v10 = W[(k0 + 8) * 512 + n];
    float v11 = W[(k0 + 9) * 512 + n];
    float h00 = __bfloat162float(__float2bfloat16_rn(v00));
    float h01 = __bfloat162float(__float2bfloat16_rn(v01));
    float h10 = __bfloat162float(__float2bfloat16_rn(v10));
    float h11 = __bfloat162float(__float2bfloat16_rn(v11));
    uint4 o;
    o.x = bf16pack(v00, v01);
    o.y = bf16pack(v10, v11);
    o.z = bf16pack(v00 - h00, v01 - h01);
    o.w = bf16pack(v10 - h10, v11 - h11);
    g_wt[idx] = o;
}

// Rigid-body derivatives, moments == 0.
__device__ __forceinline__ void derivs(const float x[12], float F0, float F1, float F2,
                                       const float Im[9], const float Iv[9], float dx[12]) {
    float V0 = x[3], V1 = x[4], V2 = x[5];
    float phi = x[6], th = x[7], ps = x[8];
    float w0 = x[9], w1 = x[10], w2 = x[11];
    float cph = cosf(phi), sph = sinf(phi);
    float cth = cosf(th), sth = sinf(th);
    float cps = cosf(ps), sps = sinf(ps);
    dx[0] = (cth * cps) * V0 + (sph * sth * cps - cph * sps) * V1 + (cph * sth * cps + sph * sps) * V2;
    dx[1] = (cth * sps) * V0 + (sph * sth * sps + cph * cps) * V1 + (cph * sth * sps - sph * cps) * V2;
    dx[2] = (-sth) * V0 + (sph * cth) * V1 + (cph * cth) * V2;
    dx[3] = F0 / 1.5f - (w1 * V2 - w2 * V1);
    dx[4] = F1 / 1.5f - (w2 * V0 - w0 * V2);
    dx[5] = F2 / 1.5f - (w0 * V1 - w1 * V0);
    float tth = tanf(th);
    float ic = 1.0f / fmaxf(cth, 1e-6f);
    dx[6] = w0 + sph * tth * w1 + cph * tth * w2;
    dx[7] = cph * w1 - sph * w2;
    dx[8] = (sph * ic) * w1 + (cph * ic) * w2;
    float Iw0 = Im[0] * w0 + Im[1] * w1 + Im[2] * w2;
    float Iw1 = Im[3] * w0 + Im[4] * w1 + Im[5] * w2;
    float Iw2 = Im[6] * w0 + Im[7] * w1 + Im[8] * w2;
    float c0 = w1 * Iw2 - w2 * Iw1;
    float c1 = w2 * Iw0 - w0 * Iw2;
    float c2 = w0 * Iw1 - w1 * Iw0;
    dx[9]  = -(Iv[0] * c0 + Iv[1] * c1 + Iv[2] * c2);
    dx[10] = -(Iv[3] * c0 + Iv[4] * c1 + Iv[5] * c2);
    dx[11] = -(Iv[6] * c0 + Iv[7] * c1 + Iv[8] * c2);
}

extern "C" __global__ void __launch_bounds__(NTH)
wm_rollout(const float* __restrict__ x_t, const float* __restrict__ act,
           const float* __restrict__ Imat_g,
           const float* __restrict__ W0, const float* __restrict__ b0v,
           const float* __restrict__ b1v, const float* __restrict__ b2v,
           const float* __restrict__ W3, const float* __restrict__ b3v,
           const int* __restrict__ seqp, float* __restrict__ out, int Bn) {
    __shared__ Smem S;
    const int tid = threadIdx.x;
    const int w = tid >> 5, lane = tid & 31;
    const int g = lane >> 2, tig = lane & 3;

    const int T = seqp[0];
    const int steps = T - 1;
    float* outF = out;
    float* outX = out + (size_t)Bn * 6 * steps;

    if (tid == 0) {
        float a = Imat_g[0], b = Imat_g[1], c = Imat_g[2];
        float d = Imat_g[3], e = Imat_g[4], f = Imat_g[5];
        float gg = Imat_g[6], h = Imat_g[7], i = Imat_g[8];
        float A = e * i - f * h, Bc = -(d * i - f * gg), C = d * h - e * gg;
        float id = 1.0f / (a * A + b * Bc + c * C);
        S.Iinv[0] = A * id;  S.Iinv[1] = (c * h - b * i) * id;   S.Iinv[2] = (b * f - c * e) * id;
        S.Iinv[3] = Bc * id; S.Iinv[4] = (a * i - c * gg) * id;  S.Iinv[5] = (c * d - a * f) * id;
        S.Iinv[6] = C * id;  S.Iinv[7] = (b * gg - a * h) * id;  S.Iinv[8] = (a * e - b * d) * id;
#pragma unroll
        for (int k = 0; k < 9; k++) S.Im[k] = Imat_g[k];
    }
    if (tid < BT) {
        const size_t bidx = (size_t)blockIdx.x * BT + tid;
#pragma unroll
        for (int s = 0; s < 12; s++) {
            float v = x_t[bidx * 12 + s];
            S.x[tid][s] = v;
            outX[bidx * 12 * T + (size_t)s * T] = v;
        }
    }
    __syncthreads();

    float ImR[9], IvR[9];
    if (tid < BT) {
#pragma unroll
        for (int k = 0; k < 9; k++) { ImR[k] = S.Im[k]; IvR[k] = S.Iinv[k]; }
    }

    const unsigned* Ah32 = (const unsigned*)S.Ah;
    const unsigned* Al32 = (const unsigned*)S.Al;
    float* h3 = (float*)S.Ah;   // overlay: 16*520 floats == Ah+Al bytes

    for (int t = 0; t < steps; t++) {
        // ---- build L0 input col-major [k][row] ----
        if (tid < BT) {
            const int n = tid;
            const size_t bidx = (size_t)blockIdx.x * BT + n;
            S.in[0 * BT + n] = S.x[n][0] * 1.2732395447351628f;
            S.in[1 * BT + n] = S.x[n][1] * 0.5f;
            S.in[2 * BT + n] = S.x[n][2] * 1.2732395447351628f;
            S.in[3 * BT + n] = S.x[n][3] * 0.1f;
            S.in[4 * BT + n] = S.x[n][4] * 0.016666666666666666f;
            S.in[5 * BT + n] = S.x[n][5] * 0.016666666666666666f;
#pragma unroll
            for (int s = 6; s < 12; s++) S.in[s * BT + n] = 0.f;
#pragma unroll
            for (int a = 0; a < 4; a++)
                S.in[(12 + a) * BT + n] = (act[(bidx * 4 + a) * T + (t + 1)] - 1500.0f) / 500.0f;
        }
        __syncthreads();

        // ---- L0 scalar: neuron c = tid; write Ah/Al[row][c] ----
        {
            const int c = tid;
            ull acc[8];
#pragma unroll
            for (int p = 0; p < 8; p++) acc[p] = 0ULL;
#pragma unroll
            for (int k = 0; k < 16; k++) {
                ull wk = pack2(W0[k * 512 + c]);
                const ull* a = (const ull*)(S.in + k * BT);
#pragma unroll
                for (int p = 0; p < 8; p++) acc[p] = fma2(a[p], wk, acc[p]);
            }
            const float bias = b0v[c];
#pragma unroll
            for (int p = 0; p < 8; p++) {
                float2 v = unpack2(acc[p]);
                float h0 = leaky(v.x + bias);
                float h1 = leaky(v.y + bias);
                __nv_bfloat16 hh0 = __float2bfloat16_rn(h0);
                __nv_bfloat16 hh1 = __float2bfloat16_rn(h1);
                S.Ah[(2 * p) * AST + c] = hh0;
                S.Ah[(2 * p + 1) * AST + c] = hh1;
                S.Al[(2 * p) * AST + c] = __float2bfloat16_rn(h0 - __bfloat162float(hh0));
                S.Al[(2 * p + 1) * AST + c] = __float2bfloat16_rn(h1 - __bfloat162float(hh1));
            }
        }
        __syncthreads();

        // ---- two MMA layers ----
#pragma unroll
        for (int la = 0; la < 2; la++) {
            float d[4][4];
#pragma unroll
            for (int nt = 0; nt < 4; nt++)
#pragma unroll
                for (int q = 0; q < 4; q++) d[nt][q] = 0.f;

            const uint4* wbase = g_wt + ((size_t)la * 65536 + w * 4096 + lane);
            uint4 bc[4], bn[4];
#pragma unroll
            for (int nt = 0; nt < 4; nt++) bc[nt] = wbase[nt * 32];

            for (int ks = 0; ks < 32; ks++) {
                if (ks < 31) {
                    const uint4* wq = wbase + (ks + 1) * 128;
#pragma unroll
                    for (int nt = 0; nt < 4; nt++) bn[nt] = wq[nt * 32];
                }
                const int kb = ks * 16;
                const int i0 = (g * AST + kb) >> 1;
                const int i1 = ((g + 8) * AST + kb) >> 1;
                unsigned ah0 = Ah32[i0 + tig];
                unsigned ah1 = Ah32[i1 + tig];
                unsigned ah2 = Ah32[i0 + tig + 4];
                unsigned ah3 = Ah32[i1 + tig + 4];
                unsigned al0 = Al32[i0 + tig];
                unsigned al1 = Al32[i1 + tig];
                unsigned al2 = Al32[i0 + tig + 4];
                unsigned al3 = Al32[i1 + tig + 4];
#pragma unroll
                for (int nt = 0; nt < 4; nt++) {
                    mma16816(d[nt], ah0, ah1, ah2, ah3, bc[nt].x, bc[nt].y);   // Ah*Bh
                    mma16816(d[nt], al0, al1, al2, al3, bc[nt].x, bc[nt].y);   // Al*Bh
                    mma16816(d[nt], ah0, ah1, ah2, ah3, bc[nt].z, bc[nt].w);   // Ah*Bl
                }
#pragma unroll
                for (int nt = 0; nt < 4; nt++) bc[nt] = bn[nt];
            }
            __syncthreads();   // all A reads done before overwrite

            if (la == 0) {
                // epilogue -> next layer's Ah/Al (rows g, g+8; cols nb, nb+1)
#pragma unroll
                for (int nt = 0; nt < 4; nt++) {
                    const int nb = w * 32 + nt * 8 + tig * 2;
                    const float bb0 = b1v[nb], bb1 = b1v[nb + 1];
                    float h00 = leaky(d[nt][0] + bb0);
                    float h01 = leaky(d[nt][1] + bb1);
                    float h10 = leaky(d[nt][2] + bb0);
                    float h11 = leaky(d[nt][3] + bb1);
                    __nv_bfloat16 a00 = __float2bfloat16_rn(h00);
                    __nv_bfloat16 a01 = __float2bfloat16_rn(h01);
                    __nv_bfloat16 a10 = __float2bfloat16_rn(h10);
                    __nv_bfloat16 a11 = __float2bfloat16_rn(h11);
                    unsigned* AhW = (unsigned*)S.Ah;
                    unsigned* AlW = (unsigned*)S.Al;
                    AhW[(g * AST + nb) >> 1] =
                        ((unsigned)__bfloat16_as_ushort(a01) << 16) | __bfloat16_as_ushort(a00);
                    AhW[((g + 8) * AST + nb) >> 1] =
                        ((unsigned)__bfloat16_as_ushort(a11) << 16) | __bfloat16_as_ushort(a10);
                    AlW[(g * AST + nb) >> 1] =
                        ((unsigned)__bfloat16_as_ushort(__float2bfloat16_rn(h01 - __bfloat162float(a01))) << 16) |
                        __bfloat16_as_ushort(__float2bfloat16_rn(h00 - __bfloat162float(a00)));
                    AlW[((g + 8) * AST + nb) >> 1] =
                        ((unsigned)__bfloat16_as_ushort(__float2bfloat16_rn(h11 - __bfloat162float(a11))) << 16) |
                        __bfloat16_as_ushort(__float2bfloat16_rn(h10 - __bfloat162float(a10)));
                }
            } else {
                // epilogue -> h3 fp32 [row][n]
#pragma unroll
                for (int nt = 0; nt < 4; nt++) {
                    const int nb = w * 32 + nt * 8 + tig * 2;
                    const float bb0 = b2v[nb], bb1 = b2v[nb + 1];
                    float2 r0, r1;
                    r0.x = leaky(d[nt][0] + bb0);
                    r0.y = leaky(d[nt][1] + bb1);
                    r1.x = leaky(d[nt][2] + bb0);
                    r1.y = leaky(d[nt][3] + bb1);
                    *(float2*)(h3 + g * AST + nb) = r0;
                    *(float2*)(h3 + (g + 8) * AST + nb) = r1;
                }
            }
            __syncthreads();
        }

        // ---- L3: 48 dots x 8 partials of 64 over h3[row][k] ----
        if (tid < 384) {
            const int o = tid >> 3, q = tid & 7;
            const int n = o / 3, c = o - n * 3;
            const float* hp = h3 + n * AST + q * 64;
            const float* wp = W3 + (q * 64) * 6 + c;
            float s = 0.f;
#pragma unroll 8
            for (int k = 0; k < 64; k++) s = fmaf(hp[k], wp[k * 6], s);
            S.part[o][q] = s;
        }
        __syncthreads();
        if (tid < 48) {
            const int n = tid / 3, c = tid - n * 3;
            const float* pp = S.part[tid];
            S.fn[n][c] = (((pp[0] + pp[1]) + (pp[2] + pp[3])) +
                          ((pp[4] + pp[5]) + (pp[6] + pp[7]))) + b3v[c];
        }
        __syncthreads();

        // ---- forces + RK4 + outputs ----
        if (tid < BT) {
            const int n = tid;
            const size_t bidx = (size_t)blockIdx.x * BT + n;
            const float F0 = S.fn[n][0] - 0.5f;
            const float F1 = S.fn[n][1] * (-0.4f) - 10.0f;
            const float F2 = S.fn[n][2] * 0.2f - 0.1f;
            float* fo = outF + bidx * 6 * steps + t;
            fo[0 * steps] = F0;
            fo[1 * steps] = F1;
            fo[2 * steps] = F2;
            fo[3 * steps] = 0.f;
            fo[4 * steps] = 0.f;
            fo[5 * steps] = 0.f;
            float xx[12];
#pragma unroll
            for (int s = 0; s < 12; s++) xx[s] = S.x[n][s];
            float k1[12], k2[12], k3[12], k4[12], tm[12];
            derivs(xx, F0, F1, F2, ImR, IvR, k1);
#pragma unroll
            for (int s = 0; s < 12; s++) tm[s] = xx[s] + 0.005f * k1[s];
            derivs(tm, F0, F1, F2, ImR, IvR, k2);
#pragma unroll
            for (int s = 0; s < 12; s++) tm[s] = xx[s] + 0.005f * k2[s];
            derivs(tm, F0, F1, F2, ImR, IvR, k3);
#pragma unroll
            for (int s = 0; s < 12; s++) tm[s] = xx[s] + 0.01f * k3[s];
            derivs(tm, F0, F1, F2, ImR, IvR, k4);
            const float w6 = (float)(0.01 / 6.0);
#pragma unroll
            for (int s = 0; s < 12; s++)
                xx[s] += w6 * (k1[s] + 2.f * k2[s] + 2.f * k3[s] + k4[s]);
            float* xo = outX + bidx * 12 * T + (t + 1);
#pragma unroll
            for (int s = 0; s < 12; s++) {
                S.x[n][s] = xx[s];
                xo[(size_t)s * T] = xx[s];
            }
        }
        __syncthreads();
    }
}

extern "C" void kernel_launch(void* const* d_in, const int* in_sizes, int n_in,
                              void* d_out, int out_size) {
    // 0: x_t, 1: act_inps, 2: I_mat, 3: seq_len, 4..11: W0,b0,W1,b1,W2,b2,W3,b3
    const float* x_t = (const float*)d_in[0];
    const float* act = (const float*)d_in[1];
    const float* Im  = (const float*)d_in[2];
    const int* seqp  = (const int*)d_in[3];
    const float* W0  = (const float*)d_in[4];
    const float* b0  = (const float*)d_in[5];
    const float* W1  = (const float*)d_in[6];
    const float* b1  = (const float*)d_in[7];
    const float* W2  = (const float*)d_in[8];
    const float* b2  = (const float*)d_in[9];
    const float* W3  = (const float*)d_in[10];
    const float* b3  = (const float*)d_in[11];

    const int Bn = in_sizes[0] / 12;
    const int grid = Bn / BT;

    wm_prep<<<256, 512>>>(W1, W2);
    wm_rollout<<<grid, NTH>>>(x_t, act, Im, W0, b0, b1, b2, W3, b3,
                              seqp, (float*)d_out, Bn);
}

// round 12
// speedup vs baseline: 2.4011x; 1.6074x over previous
#include <cuda_runtime.h>
#include <cuda_bf16.h>
#include <math.h>
#include <stdint.h>

#define NTH 512
#define BT 16
#define HD 512
#define AST 520   // activation row stride in elems (1040B -> conflict-free ldmatrix phases)

typedef unsigned long long ull;

// Fragment-packed weights: uint4 per (layer, warp, kstep, ntile, lane)
// idx = ((l*16 + w)*32 + ks)*128 + nt*32 + lane ; payload = {bh0, bh1, bl0, bl1}
__device__ __align__(16) uint4 g_wt[2 * 16 * 32 * 4 * 32];

struct Smem {
    __nv_bfloat16 Ah[BT * AST];   // activations hi: [row][k]
    __nv_bfloat16 Al[BT * AST];   // lo
    float in[16 * BT];            // L0 input col-major [k][row]
    float x[BT][12];
    float fn[BT][3];
    float part[48][8];
    float Im[9], Iinv[9];
};

__device__ __forceinline__ float leaky(float v) { return v >= 0.f ? v : 0.01f * v; }
__device__ __forceinline__ ull fma2(ull a, ull b, ull c) {
    ull d;
    asm("fma.rn.f32x2 %0, %1, %2, %3;" : "=l"(d) : "l"(a), "l"(b), "l"(c));
    return d;
}
__device__ __forceinline__ ull pack2(float x) {
    ull r;
    asm("mov.b64 %0, {%1, %1};" : "=l"(r) : "f"(x));
    return r;
}
__device__ __forceinline__ float2 unpack2(ull v) {
    float2 f;
    asm("mov.b64 {%0, %1}, %2;" : "=f"(f.x), "=f"(f.y) : "l"(v));
    return f;
}
__device__ __forceinline__ uint32_t s2u(const void* p) {
    uint32_t a;
    asm("{ .reg .u64 t; cvta.to.shared.u64 t, %1; cvt.u32.u64 %0, t; }" : "=r"(a) : "l"(p));
    return a;
}

// mma.m16n8k16 row.col bf16 -> f32 accum (portable HMMA, sm_80+)
__device__ __forceinline__ void mma16816(float d[4], unsigned a0, unsigned a1, unsigned a2,
                                         unsigned a3, unsigned b0, unsigned b1) {
    asm volatile(
        "mma.sync.aligned.m16n8k16.row.col.f32.bf16.bf16.f32 "
        "{%0,%1,%2,%3}, {%4,%5,%6,%7}, {%8,%9}, {%0,%1,%2,%3};"
        : "+f"(d[0]), "+f"(d[1]), "+f"(d[2]), "+f"(d[3])
        : "r"(a0), "r"(a1), "r"(a2), "r"(a3), "r"(b0), "r"(b1));
}

// ldmatrix x4: loads full m16k16 b16 A-fragment (lane addr = one 16B row)
__device__ __forceinline__ void ldsm4(unsigned& r0, unsigned& r1, unsigned& r2, unsigned& r3,
                                      uint32_t addr) {
    asm volatile("ldmatrix.sync.aligned.m8n8.x4.shared.b16 {%0,%1,%2,%3}, [%4];"
                 : "=r"(r0), "=r"(r1), "=r"(r2), "=r"(r3) : "r"(addr));
}

__device__ __forceinline__ unsigned bf16pack(float lo_elem, float hi_elem) {
    unsigned short s0 = __bfloat16_as_ushort(__float2bfloat16_rn(lo_elem));
    unsigned short s1 = __bfloat16_as_ushort(__float2bfloat16_rn(hi_elem));
    return ((unsigned)s1 << 16) | s0;
}

// ---------------- prep: pack W1/W2 into fragment order, bf16 hi/lo ----------------
extern "C" __global__ void wm_prep(const float* __restrict__ W1, const float* __restrict__ W2) {
    int idx = blockIdx.x * blockDim.x + threadIdx.x;   // 131072 total
    int lane = idx & 31;
    int nt = (idx >> 5) & 3;
    int ks = (idx >> 7) & 31;
    int w = (idx >> 12) & 15;
    int l = idx >> 16;
    int g = lane >> 2, tig = lane & 3;
    int k0 = ks * 16 + tig * 2;
    int n = (w * 4 + nt) * 8 + g;
    const float* W = l ? W2 : W1;
    float v00 = W[(k0 + 0) * 512 + n];
    float v01 = W[(k0 + 1) * 512 + n];
    float v10 = W[(k0 + 8) * 512 + n];
    float v11 = W[(k0 + 9) * 512 + n];
    float h00 = __bfloat162float(__float2bfloat16_rn(v00));
    float h01 = __bfloat162float(__float2bfloat16_rn(v01));
    float h10 = __bfloat162float(__float2bfloat16_rn(v10));
    float h11 = __bfloat162float(__float2bfloat16_rn(v11));
    uint4 o;
    o.x = bf16pack(v00, v01);
    o.y = bf16pack(v10, v11);
    o.z = bf16pack(v00 - h00, v01 - h01);
    o.w = bf16pack(v10 - h10, v11 - h11);
    g_wt[idx] = o;
}

// Rigid-body derivatives, moments == 0.
__device__ __forceinline__ void derivs(const float x[12], float F0, float F1, float F2,
                                       const float Im[9], const float Iv[9], float dx[12]) {
    float V0 = x[3], V1 = x[4], V2 = x[5];
    float phi = x[6], th = x[7], ps = x[8];
    float w0 = x[9], w1 = x[10], w2 = x[11];
    float cph = cosf(phi), sph = sinf(phi);
    float cth = cosf(th), sth = sinf(th);
    float cps = cosf(ps), sps = sinf(ps);
    dx[0] = (cth * cps) * V0 + (sph * sth * cps - cph * sps) * V1 + (cph * sth * cps + sph * sps) * V2;
    dx[1] = (cth * sps) * V0 + (sph * sth * sps + cph * cps) * V1 + (cph * sth * sps - sph * cps) * V2;
    dx[2] = (-sth) * V0 + (sph * cth) * V1 + (cph * cth) * V2;
    dx[3] = F0 / 1.5f - (w1 * V2 - w2 * V1);
    dx[4] = F1 / 1.5f - (w2 * V0 - w0 * V2);
    dx[5] = F2 / 1.5f - (w0 * V1 - w1 * V0);
    float tth = tanf(th);
    float ic = 1.0f / fmaxf(cth, 1e-6f);
    dx[6] = w0 + sph * tth * w1 + cph * tth * w2;
    dx[7] = cph * w1 - sph * w2;
    dx[8] = (sph * ic) * w1 + (cph * ic) * w2;
    float Iw0 = Im[0] * w0 + Im[1] * w1 + Im[2] * w2;
    float Iw1 = Im[3] * w0 + Im[4] * w1 + Im[5] * w2;
    float Iw2 = Im[6] * w0 + Im[7] * w1 + Im[8] * w2;
    float c0 = w1 * Iw2 - w2 * Iw1;
    float c1 = w2 * Iw0 - w0 * Iw2;
    float c2 = w0 * Iw1 - w1 * Iw0;
    dx[9]  = -(Iv[0] * c0 + Iv[1] * c1 + Iv[2] * c2);
    dx[10] = -(Iv[3] * c0 + Iv[4] * c1 + Iv[5] * c2);
    dx[11] = -(Iv[6] * c0 + Iv[7] * c1 + Iv[8] * c2);
}

extern "C" __global__ void __launch_bounds__(NTH)
wm_rollout(const float* __restrict__ x_t, const float* __restrict__ act,
           const float* __restrict__ Imat_g,
           const float* __restrict__ W0, const float* __restrict__ b0v,
           const float* __restrict__ b1v, const float* __restrict__ b2v,
           const float* __restrict__ W3, const float* __restrict__ b3v,
           const int* __restrict__ seqp, float* __restrict__ out, int Bn) {
    __shared__ Smem S;
    const int tid = threadIdx.x;
    const int w = tid >> 5, lane = tid & 31;
    const int g = lane >> 2, tig = lane & 3;

    const int T = seqp[0];
    const int steps = T - 1;
    float* outF = out;
    float* outX = out + (size_t)Bn * 6 * steps;

    if (tid == 0) {
        float a = Imat_g[0], b = Imat_g[1], c = Imat_g[2];
        float d = Imat_g[3], e = Imat_g[4], f = Imat_g[5];
        float gg = Imat_g[6], h = Imat_g[7], i = Imat_g[8];
        float A = e * i - f * h, Bc = -(d * i - f * gg), C = d * h - e * gg;
        float id = 1.0f / (a * A + b * Bc + c * C);
        S.Iinv[0] = A * id;  S.Iinv[1] = (c * h - b * i) * id;   S.Iinv[2] = (b * f - c * e) * id;
        S.Iinv[3] = Bc * id; S.Iinv[4] = (a * i - c * gg) * id;  S.Iinv[5] = (c * d - a * f) * id;
        S.Iinv[6] = C * id;  S.Iinv[7] = (b * gg - a * h) * id;  S.Iinv[8] = (a * e - b * d) * id;
#pragma unroll
        for (int k = 0; k < 9; k++) S.Im[k] = Imat_g[k];
    }
    if (tid < BT) {
        const size_t bidx = (size_t)blockIdx.x * BT + tid;
#pragma unroll
        for (int s = 0; s < 12; s++) {
            float v = x_t[bidx * 12 + s];
            S.x[tid][s] = v;
            outX[bidx * 12 * T + (size_t)s * T] = v;
        }
    }
    __syncthreads();

    float ImR[9], IvR[9];
    if (tid < BT) {
#pragma unroll
        for (int k = 0; k < 9; k++) { ImR[k] = S.Im[k]; IvR[k] = S.Iinv[k]; }
    }

    // ldmatrix lane base addresses: row = lane&15, k offset += (lane>>4)*8
    const uint32_t ahBase = s2u(S.Ah) + (uint32_t)(((lane & 15) * AST + ((lane >> 4) << 3)) * 2);
    const uint32_t alBase = ahBase + BT * AST * 2;
    float* h3 = (float*)S.Ah;   // overlay: 16*520 floats == Ah+Al bytes

    for (int t = 0; t < steps; t++) {
        // ---- build L0 input col-major [k][row] ----
        if (tid < BT) {
            const int n = tid;
            const size_t bidx = (size_t)blockIdx.x * BT + n;
            S.in[0 * BT + n] = S.x[n][0] * 1.2732395447351628f;
            S.in[1 * BT + n] = S.x[n][1] * 0.5f;
            S.in[2 * BT + n] = S.x[n][2] * 1.2732395447351628f;
            S.in[3 * BT + n] = S.x[n][3] * 0.1f;
            S.in[4 * BT + n] = S.x[n][4] * 0.016666666666666666f;
            S.in[5 * BT + n] = S.x[n][5] * 0.016666666666666666f;
#pragma unroll
            for (int s = 6; s < 12; s++) S.in[s * BT + n] = 0.f;
#pragma unroll
            for (int a = 0; a < 4; a++)
                S.in[(12 + a) * BT + n] = (act[(bidx * 4 + a) * T + (t + 1)] - 1500.0f) / 500.0f;
        }
        __syncthreads();

        // ---- L0 scalar: neuron c = tid; write Ah/Al[row][c] ----
        {
            const int c = tid;
            ull acc[8];
#pragma unroll
            for (int p = 0; p < 8; p++) acc[p] = 0ULL;
#pragma unroll
            for (int k = 0; k < 16; k++) {
                ull wk = pack2(W0[k * 512 + c]);
                const ull* a = (const ull*)(S.in + k * BT);
#pragma unroll
                for (int p = 0; p < 8; p++) acc[p] = fma2(a[p], wk, acc[p]);
            }
            const float bias = b0v[c];
#pragma unroll
            for (int p = 0; p < 8; p++) {
                float2 v = unpack2(acc[p]);
                float h0 = leaky(v.x + bias);
                float h1 = leaky(v.y + bias);
                __nv_bfloat16 hh0 = __float2bfloat16_rn(h0);
                __nv_bfloat16 hh1 = __float2bfloat16_rn(h1);
                S.Ah[(2 * p) * AST + c] = hh0;
                S.Ah[(2 * p + 1) * AST + c] = hh1;
                S.Al[(2 * p) * AST + c] = __float2bfloat16_rn(h0 - __bfloat162float(hh0));
                S.Al[(2 * p + 1) * AST + c] = __float2bfloat16_rn(h1 - __bfloat162float(hh1));
            }
        }
        __syncthreads();

        // ---- two MMA layers ----
#pragma unroll
        for (int la = 0; la < 2; la++) {
            float d[4][4];
#pragma unroll
            for (int nt = 0; nt < 4; nt++)
#pragma unroll
                for (int q = 0; q < 4; q++) d[nt][q] = 0.f;

            const uint4* wbase = g_wt + ((size_t)la * 65536 + w * 4096 + lane);
            uint4 bc[4], bn[4];
#pragma unroll
            for (int nt = 0; nt < 4; nt++) bc[nt] = wbase[nt * 32];

            for (int ks = 0; ks < 32; ks++) {
                // A fragments via 2x ldmatrix.x4
                unsigned ah0, ah1, ah2, ah3, al0, al1, al2, al3;
                ldsm4(ah0, ah1, ah2, ah3, ahBase + ks * 32);   // kb*2 bytes = ks*16*2
                ldsm4(al0, al1, al2, al3, alBase + ks * 32);
                // prefetch next W fragments
                if (ks < 31) {
                    const uint4* wq = wbase + (ks + 1) * 128;
#pragma unroll
                    for (int nt = 0; nt < 4; nt++) bn[nt] = wq[nt * 32];
                }
                // term-major issue: same-accumulator MMAs are 4 apart -> pipelined chains
#pragma unroll
                for (int nt = 0; nt < 4; nt++)
                    mma16816(d[nt], ah0, ah1, ah2, ah3, bc[nt].x, bc[nt].y);   // Ah*Bh
#pragma unroll
                for (int nt = 0; nt < 4; nt++)
                    mma16816(d[nt], al0, al1, al2, al3, bc[nt].x, bc[nt].y);   // Al*Bh
#pragma unroll
                for (int nt = 0; nt < 4; nt++)
                    mma16816(d[nt], ah0, ah1, ah2, ah3, bc[nt].z, bc[nt].w);   // Ah*Bl
#pragma unroll
                for (int nt = 0; nt < 4; nt++) bc[nt] = bn[nt];
            }
            __syncthreads();   // all A reads done before overwrite

            if (la == 0) {
                // epilogue -> next layer's Ah/Al (rows g, g+8; cols nb, nb+1)
#pragma unroll
                for (int nt = 0; nt < 4; nt++) {
                    const int nb = w * 32 + nt * 8 + tig * 2;
                    const float bb0 = b1v[nb], bb1 = b1v[nb + 1];
                    float h00 = leaky(d[nt][0] + bb0);
                    float h01 = leaky(d[nt][1] + bb1);
                    float h10 = leaky(d[nt][2] + bb0);
                    float h11 = leaky(d[nt][3] + bb1);
                    __nv_bfloat16 a00 = __float2bfloat16_rn(h00);
                    __nv_bfloat16 a01 = __float2bfloat16_rn(h01);
                    __nv_bfloat16 a10 = __float2bfloat16_rn(h10);
                    __nv_bfloat16 a11 = __float2bfloat16_rn(h11);
                    unsigned* AhW = (unsigned*)S.Ah;
                    unsigned* AlW = (unsigned*)S.Al;
                    AhW[(g * AST + nb) >> 1] =
                        ((unsigned)__bfloat16_as_ushort(a01) << 16) | __bfloat16_as_ushort(a00);
                    AhW[((g + 8) * AST + nb) >> 1] =
                        ((unsigned)__bfloat16_as_ushort(a11) << 16) | __bfloat16_as_ushort(a10);
                    AlW[(g * AST + nb) >> 1] =
                        ((unsigned)__bfloat16_as_ushort(__float2bfloat16_rn(h01 - __bfloat162float(a01))) << 16) |
                        __bfloat16_as_ushort(__float2bfloat16_rn(h00 - __bfloat162float(a00)));
                    AlW[((g + 8) * AST + nb) >> 1] =
                        ((unsigned)__bfloat16_as_ushort(__float2bfloat16_rn(h11 - __bfloat162float(a11))) << 16) |
                        __bfloat16_as_ushort(__float2bfloat16_rn(h10 - __bfloat162float(a10)));
                }
            } else {
                // epilogue -> h3 fp32 [row][n]
#pragma unroll
                for (int nt = 0; nt < 4; nt++) {
                    const int nb = w * 32 + nt * 8 + tig * 2;
                    const float bb0 = b2v[nb], bb1 = b2v[nb + 1];
                    float2 r0, r1;
                    r0.x = leaky(d[nt][0] + bb0);
                    r0.y = leaky(d[nt][1] + bb1);
                    r1.x = leaky(d[nt][2] + bb0);
                    r1.y = leaky(d[nt][3] + bb1);
                    *(float2*)(h3 + g * AST + nb) = r0;
                    *(float2*)(h3 + (g + 8) * AST + nb) = r1;
                }
            }
            __syncthreads();
        }

        // ---- L3: 48 dots x 8 partials of 64 over h3[row][k] ----
        if (tid < 384) {
            const int o = tid >> 3, q = tid & 7;
            const int n = o / 3, c = o - n * 3;
            const float* hp = h3 + n * AST + q * 64;
            const float* wp = W3 + (q * 64) * 6 + c;
            float s = 0.f;
#pragma unroll 8
            for (int k = 0; k < 64; k++) s = fmaf(hp[k], wp[k * 6], s);
            S.part[o][q] = s;
        }
        __syncthreads();
        if (tid < 48) {
            const int n = tid / 3, c = tid - n * 3;
            const float* pp = S.part[tid];
            S.fn[n][c] = (((pp[0] + pp[1]) + (pp[2] + pp[3])) +
                          ((pp[4] + pp[5]) + (pp[6] + pp[7]))) + b3v[c];
        }
        __syncthreads();

        // ---- forces + RK4 + outputs ----
        if (tid < BT) {
            const int n = tid;
            const size_t bidx = (size_t)blockIdx.x * BT + n;
            const float F0 = S.fn[n][0] - 0.5f;
            const float F1 = S.fn[n][1] * (-0.4f) - 10.0f;
            const float F2 = S.fn[n][2] * 0.2f - 0.1f;
            float* fo = outF + bidx * 6 * steps + t;
            fo[0 * steps] = F0;
            fo[1 * steps] = F1;
            fo[2 * steps] = F2;
            fo[3 * steps] = 0.f;
            fo[4 * steps] = 0.f;
            fo[5 * steps] = 0.f;
            float xx[12];
#pragma unroll
            for (int s = 0; s < 12; s++) xx[s] = S.x[n][s];
            float k1[12], k2[12], k3[12], k4[12], tm[12];
            derivs(xx, F0, F1, F2, ImR, IvR, k1);
#pragma unroll
            for (int s = 0; s < 12; s++) tm[s] = xx[s] + 0.005f * k1[s];
            derivs(tm, F0, F1, F2, ImR, IvR, k2);
#pragma unroll
            for (int s = 0; s < 12; s++) tm[s] = xx[s] + 0.005f * k2[s];
            derivs(tm, F0, F1, F2, ImR, IvR, k3);
#pragma unroll
            for (int s = 0; s < 12; s++) tm[s] = xx[s] + 0.01f * k3[s];
            derivs(tm, F0, F1, F2, ImR, IvR, k4);
            const float w6 = (float)(0.01 / 6.0);
#pragma unroll
            for (int s = 0; s < 12; s++)
                xx[s] += w6 * (k1[s] + 2.f * k2[s] + 2.f * k3[s] + k4[s]);
            float* xo = outX + bidx * 12 * T + (t + 1);
#pragma unroll
            for (int s = 0; s < 12; s++) {
                S.x[n][s] = xx[s];
                xo[(size_t)s * T] = xx[s];
            }
        }
        __syncthreads();
    }
}

extern "C" void kernel_launch(void* const* d_in, const int* in_sizes, int n_in,
                              void* d_out, int out_size) {
    // 0: x_t, 1: act_inps, 2: I_mat, 3: seq_len, 4..11: W0,b0,W1,b1,W2,b2,W3,b3
    const float* x_t = (const float*)d_in[0];
    const float* act = (const float*)d_in[1];
    const float* Im  = (const float*)d_in[2];
    const int* seqp  = (const int*)d_in[3];
    const float* W0  = (const float*)d_in[4];
    const float* b0  = (const float*)d_in[5];
    const float* W1  = (const float*)d_in[6];
    const float* b1  = (const float*)d_in[7];
    const float* W2  = (const float*)d_in[8];
    const float* b2  = (const float*)d_in[9];
    const float* W3  = (const float*)d_in[10];
    const float* b3  = (const float*)d_in[11];

    const int Bn = in_sizes[0] / 12;
    const int grid = Bn / BT;

    wm_prep<<<256, 512>>>(W1, W2);
    wm_rollout<<<grid, NTH>>>(x_t, act, Im, W0, b0, b1, b2, W3, b3,
                              seqp, (float*)d_out, Bn);
}

// round 13
// speedup vs baseline: 2.5965x; 1.0814x over previous
#include <cuda_runtime.h>
#include <cuda_bf16.h>
#include <math.h>
#include <stdint.h>

#define NTH 512
#define BT 16
#define HD 512
#define AST 520   // activation row stride in elems (1040B -> conflict-free ldmatrix phases)

typedef unsigned long long ull;

// Fragment-packed weights: uint4 per (layer, warp, kstep, ntile, lane)
// idx = ((l*16 + w)*32 + ks)*128 + nt*32 + lane ; payload = {bh0, bh1, bl0, bl1}
__device__ __align__(16) uint4 g_wt[2 * 16 * 32 * 4 * 32];

struct Smem {
    __nv_bfloat16 Ah[BT * AST];   // activations hi: [row][k]
    __nv_bfloat16 Al[BT * AST];   // lo
    float in[16 * BT];            // L0 input col-major [k][row]
    float x[BT][12];
    float fn[BT][3];
    float part[48][8];
    float Im[9], Iinv[9];
};

__device__ __forceinline__ float leaky(float v) { return v >= 0.f ? v : 0.01f * v; }
__device__ __forceinline__ ull fma2(ull a, ull b, ull c) {
    ull d;
    asm("fma.rn.f32x2 %0, %1, %2, %3;" : "=l"(d) : "l"(a), "l"(b), "l"(c));
    return d;
}
__device__ __forceinline__ ull pack2(float x) {
    ull r;
    asm("mov.b64 %0, {%1, %1};" : "=l"(r) : "f"(x));
    return r;
}
__device__ __forceinline__ float2 unpack2(ull v) {
    float2 f;
    asm("mov.b64 {%0, %1}, %2;" : "=f"(f.x), "=f"(f.y) : "l"(v));
    return f;
}
__device__ __forceinline__ uint32_t s2u(const void* p) {
    uint32_t a;
    asm("{ .reg .u64 t; cvta.to.shared.u64 t, %1; cvt.u32.u64 %0, t; }" : "=r"(a) : "l"(p));
    return a;
}

// mma.m16n8k16 row.col bf16 -> f32 accum (portable HMMA, sm_80+)
__device__ __forceinline__ void mma16816(float d[4], unsigned a0, unsigned a1, unsigned a2,
                                         unsigned a3, unsigned b0, unsigned b1) {
    asm volatile(
        "mma.sync.aligned.m16n8k16.row.col.f32.bf16.bf16.f32 "
        "{%0,%1,%2,%3}, {%4,%5,%6,%7}, {%8,%9}, {%0,%1,%2,%3};"
        : "+f"(d[0]), "+f"(d[1]), "+f"(d[2]), "+f"(d[3])
        : "r"(a0), "r"(a1), "r"(a2), "r"(a3), "r"(b0), "r"(b1));
}

// ldmatrix x4: loads full m16k16 b16 A-fragment (lane addr = one 16B row)
__device__ __forceinline__ void ldsm4(unsigned& r0, unsigned& r1, unsigned& r2, unsigned& r3,
                                      uint32_t addr) {
    asm volatile("ldmatrix.sync.aligned.m8n8.x4.shared.b16 {%0,%1,%2,%3}, [%4];"
                 : "=r"(r0), "=r"(r1), "=r"(r2), "=r"(r3) : "r"(addr));
}

__device__ __forceinline__ unsigned bf16pack(float lo_elem, float hi_elem) {
    unsigned short s0 = __bfloat16_as_ushort(__float2bfloat16_rn(lo_elem));
    unsigned short s1 = __bfloat16_as_ushort(__float2bfloat16_rn(hi_elem));
    return ((unsigned)s1 << 16) | s0;
}

// ---------------- prep: pack W1/W2 into fragment order, bf16 hi/lo ----------------
extern "C" __global__ void wm_prep(const float* __restrict__ W1, const float* __restrict__ W2) {
    int idx = blockIdx.x * blockDim.x + threadIdx.x;   // 131072 total
    int lane = idx & 31;
    int nt = (idx >> 5) & 3;
    int ks = (idx >> 7) & 31;
    int w = (idx >> 12) & 15;
    int l = idx >> 16;
    int g = lane >> 2, tig = lane & 3;
    int k0 = ks * 16 + tig * 2;
    int n = (w * 4 + nt) * 8 + g;
    const float* W = l ? W2 : W1;
    float v00 = W[(k0 + 0) * 512 + n];
    float v01 = W[(k0 + 1) * 512 + n];
    float v10 = W[(k0 + 8) * 512 + n];
    float v11 = W[(k0 + 9) * 512 + n];
    float h00 = __bfloat162float(__float2bfloat16_rn(v00));
    float h01 = __bfloat162float(__float2bfloat16_rn(v01));
    float h10 = __bfloat162float(__float2bfloat16_rn(v10));
    float h11 = __bfloat162float(__float2bfloat16_rn(v11));
    uint4 o;
    o.x = bf16pack(v00, v01);
    o.y = bf16pack(v10, v11);
    o.z = bf16pack(v00 - h00, v01 - h01);
    o.w = bf16pack(v10 - h10, v11 - h11);
    g_wt[idx] = o;
}

// Rigid-body derivatives, moments == 0. sincosf-based.
__device__ __forceinline__ void derivs(const float x[12], float F0, float F1, float F2,
                                       const float Im[9], const float Iv[9], float dx[12]) {
    float V0 = x[3], V1 = x[4], V2 = x[5];
    float phi = x[6], th = x[7], ps = x[8];
    float w0 = x[9], w1 = x[10], w2 = x[11];
    float sph, cph, sth, cth, sps, cps;
    sincosf(phi, &sph, &cph);
    sincosf(th, &sth, &cth);
    sincosf(ps, &sps, &cps);
    dx[0] = (cth * cps) * V0 + (sph * sth * cps - cph * sps) * V1 + (cph * sth * cps + sph * sps) * V2;
    dx[1] = (cth * sps) * V0 + (sph * sth * sps + cph * cps) * V1 + (cph * sth * sps - sph * cps) * V2;
    dx[2] = (-sth) * V0 + (sph * cth) * V1 + (cph * cth) * V2;
    dx[3] = F0 / 1.5f - (w1 * V2 - w2 * V1);
    dx[4] = F1 / 1.5f - (w2 * V0 - w0 * V2);
    dx[5] = F2 / 1.5f - (w0 * V1 - w1 * V0);
    float ic = 1.0f / fmaxf(cth, 1e-6f);      // 1/clip(cos)
    float tth = sth * ic;                      // == tan(th) whenever cth > eps (always here)
    dx[6] = w0 + sph * tth * w1 + cph * tth * w2;
    dx[7] = cph * w1 - sph * w2;
    dx[8] = (sph * ic) * w1 + (cph * ic) * w2;
    float Iw0 = Im[0] * w0 + Im[1] * w1 + Im[2] * w2;
    float Iw1 = Im[3] * w0 + Im[4] * w1 + Im[5] * w2;
    float Iw2 = Im[6] * w0 + Im[7] * w1 + Im[8] * w2;
    float c0 = w1 * Iw2 - w2 * Iw1;
    float c1 = w2 * Iw0 - w0 * Iw2;
    float c2 = w0 * Iw1 - w1 * Iw0;
    dx[9]  = -(Iv[0] * c0 + Iv[1] * c1 + Iv[2] * c2);
    dx[10] = -(Iv[3] * c0 + Iv[4] * c1 + Iv[5] * c2);
    dx[11] = -(Iv[6] * c0 + Iv[7] * c1 + Iv[8] * c2);
}

extern "C" __global__ void __launch_bounds__(NTH)
wm_rollout(const float* __restrict__ x_t, const float* __restrict__ act,
           const float* __restrict__ Imat_g,
           const float* __restrict__ W0, const float* __restrict__ b0v,
           const float* __restrict__ b1v, const float* __restrict__ b2v,
           const float* __restrict__ W3, const float* __restrict__ b3v,
           const int* __restrict__ seqp, float* __restrict__ out, int Bn) {
    __shared__ Smem S;
    const int tid = threadIdx.x;
    const int w = tid >> 5, lane = tid & 31;
    const int g = lane >> 2, tig = lane & 3;

    const int T = seqp[0];
    const int steps = T - 1;
    float* outF = out;
    float* outX = out + (size_t)Bn * 6 * steps;

    if (tid == 0) {
        float a = Imat_g[0], b = Imat_g[1], c = Imat_g[2];
        float d = Imat_g[3], e = Imat_g[4], f = Imat_g[5];
        float gg = Imat_g[6], h = Imat_g[7], i = Imat_g[8];
        float A = e * i - f * h, Bc = -(d * i - f * gg), C = d * h - e * gg;
        float id = 1.0f / (a * A + b * Bc + c * C);
        S.Iinv[0] = A * id;  S.Iinv[1] = (c * h - b * i) * id;   S.Iinv[2] = (b * f - c * e) * id;
        S.Iinv[3] = Bc * id; S.Iinv[4] = (a * i - c * gg) * id;  S.Iinv[5] = (c * d - a * f) * id;
        S.Iinv[6] = C * id;  S.Iinv[7] = (b * gg - a * h) * id;  S.Iinv[8] = (a * e - b * d) * id;
#pragma unroll
        for (int k = 0; k < 9; k++) S.Im[k] = Imat_g[k];
    }
    if (tid < BT) {
        const int n = tid;
        const size_t bidx = (size_t)blockIdx.x * BT + n;
#pragma unroll
        for (int s = 0; s < 12; s++) {
            float v = x_t[bidx * 12 + s];
            S.x[n][s] = v;
            outX[bidx * 12 * T + (size_t)s * T] = v;
        }
        // build L0 input for t=0
        S.in[0 * BT + n] = S.x[n][0] * 1.2732395447351628f;
        S.in[1 * BT + n] = S.x[n][1] * 0.5f;
        S.in[2 * BT + n] = S.x[n][2] * 1.2732395447351628f;
        S.in[3 * BT + n] = S.x[n][3] * 0.1f;
        S.in[4 * BT + n] = S.x[n][4] * 0.016666666666666666f;
        S.in[5 * BT + n] = S.x[n][5] * 0.016666666666666666f;
#pragma unroll
        for (int s = 6; s < 12; s++) S.in[s * BT + n] = 0.f;
#pragma unroll
        for (int a = 0; a < 4; a++)
            S.in[(12 + a) * BT + n] = (act[(bidx * 4 + a) * T + 1] - 1500.0f) / 500.0f;
    }
    __syncthreads();

    float ImR[9], IvR[9];
    if (tid < BT) {
#pragma unroll
        for (int k = 0; k < 9; k++) { ImR[k] = S.Im[k]; IvR[k] = S.Iinv[k]; }
    }

    // ldmatrix lane base addresses: row = lane&15, k offset += (lane>>4)*8
    const uint32_t ahBase = s2u(S.Ah) + (uint32_t)(((lane & 15) * AST + ((lane >> 4) << 3)) * 2);
    const uint32_t alBase = ahBase + BT * AST * 2;
    float* h3 = (float*)S.Ah;   // overlay: 16*520 floats == Ah+Al bytes

    for (int t = 0; t < steps; t++) {
        // ---- L0 scalar: neuron c = tid; write Ah/Al[row][c] ----
        {
            const int c = tid;
            ull acc[8];
#pragma unroll
            for (int p = 0; p < 8; p++) acc[p] = 0ULL;
#pragma unroll
            for (int k = 0; k < 16; k++) {
                ull wk = pack2(W0[k * 512 + c]);
                const ull* a = (const ull*)(S.in + k * BT);
#pragma unroll
                for (int p = 0; p < 8; p++) acc[p] = fma2(a[p], wk, acc[p]);
            }
            const float bias = b0v[c];
#pragma unroll
            for (int p = 0; p < 8; p++) {
                float2 v = unpack2(acc[p]);
                float h0 = leaky(v.x + bias);
                float h1 = leaky(v.y + bias);
                __nv_bfloat16 hh0 = __float2bfloat16_rn(h0);
                __nv_bfloat16 hh1 = __float2bfloat16_rn(h1);
                S.Ah[(2 * p) * AST + c] = hh0;
                S.Ah[(2 * p + 1) * AST + c] = hh1;
                S.Al[(2 * p) * AST + c] = __float2bfloat16_rn(h0 - __bfloat162float(hh0));
                S.Al[(2 * p + 1) * AST + c] = __float2bfloat16_rn(h1 - __bfloat162float(hh1));
            }
        }
        __syncthreads();

        // ---- two MMA layers ----
#pragma unroll
        for (int la = 0; la < 2; la++) {
            float d[4][4];
#pragma unroll
            for (int nt = 0; nt < 4; nt++)
#pragma unroll
                for (int q = 0; q < 4; q++) d[nt][q] = 0.f;

            const uint4* wbase = g_wt + ((size_t)la * 65536 + w * 4096 + lane);
            // 3-deep W register ring (prefetch distance covers L2 latency)
            uint4 wreg[3][4];
#pragma unroll
            for (int s = 0; s < 3; s++)
#pragma unroll
                for (int nt = 0; nt < 4; nt++) wreg[s][nt] = wbase[s * 128 + nt * 32];

#pragma unroll
            for (int ks = 0; ks < 32; ks++) {
                const int slot = ks % 3;
                unsigned ah0, ah1, ah2, ah3, al0, al1, al2, al3;
                ldsm4(ah0, ah1, ah2, ah3, ahBase + ks * 32);
                ldsm4(al0, al1, al2, al3, alBase + ks * 32);
                // term-major issue: same-accumulator MMAs are 4 apart
#pragma unroll
                for (int nt = 0; nt < 4; nt++)
                    mma16816(d[nt], ah0, ah1, ah2, ah3, wreg[slot][nt].x, wreg[slot][nt].y);
#pragma unroll
                for (int nt = 0; nt < 4; nt++)
                    mma16816(d[nt], al0, al1, al2, al3, wreg[slot][nt].x, wreg[slot][nt].y);
#pragma unroll
                for (int nt = 0; nt < 4; nt++)
                    mma16816(d[nt], ah0, ah1, ah2, ah3, wreg[slot][nt].z, wreg[slot][nt].w);
                if (ks + 3 < 32) {
#pragma unroll
                    for (int nt = 0; nt < 4; nt++)
                        wreg[slot][nt] = wbase[(ks + 3) * 128 + nt * 32];
                }
            }
            __syncthreads();   // all A reads done before overwrite

            if (la == 0) {
                // epilogue -> next layer's Ah/Al (rows g, g+8; cols nb, nb+1)
#pragma unroll
                for (int nt = 0; nt < 4; nt++) {
                    const int nb = w * 32 + nt * 8 + tig * 2;
                    const float bb0 = b1v[nb], bb1 = b1v[nb + 1];
                    float h00 = leaky(d[nt][0] + bb0);
                    float h01 = leaky(d[nt][1] + bb1);
                    float h10 = leaky(d[nt][2] + bb0);
                    float h11 = leaky(d[nt][3] + bb1);
                    __nv_bfloat16 a00 = __float2bfloat16_rn(h00);
                    __nv_bfloat16 a01 = __float2bfloat16_rn(h01);
                    __nv_bfloat16 a10 = __float2bfloat16_rn(h10);
                    __nv_bfloat16 a11 = __float2bfloat16_rn(h11);
                    unsigned* AhW = (unsigned*)S.Ah;
                    unsigned* AlW = (unsigned*)S.Al;
                    AhW[(g * AST + nb) >> 1] =
                        ((unsigned)__bfloat16_as_ushort(a01) << 16) | __bfloat16_as_ushort(a00);
                    AhW[((g + 8) * AST + nb) >> 1] =
                        ((unsigned)__bfloat16_as_ushort(a11) << 16) | __bfloat16_as_ushort(a10);
                    AlW[(g * AST + nb) >> 1] =
                        ((unsigned)__bfloat16_as_ushort(__float2bfloat16_rn(h01 - __bfloat162float(a01))) << 16) |
                        __bfloat16_as_ushort(__float2bfloat16_rn(h00 - __bfloat162float(a00)));
                    AlW[((g + 8) * AST + nb) >> 1] =
                        ((unsigned)__bfloat16_as_ushort(__float2bfloat16_rn(h11 - __bfloat162float(a11))) << 16) |
                        __bfloat16_as_ushort(__float2bfloat16_rn(h10 - __bfloat162float(a10)));
                }
            } else {
                // epilogue -> h3 fp32 [row][n]
#pragma unroll
                for (int nt = 0; nt < 4; nt++) {
                    const int nb = w * 32 + nt * 8 + tig * 2;
                    const float bb0 = b2v[nb], bb1 = b2v[nb + 1];
                    float2 r0, r1;
                    r0.x = leaky(d[nt][0] + bb0);
                    r0.y = leaky(d[nt][1] + bb1);
                    r1.x = leaky(d[nt][2] + bb0);
                    r1.y = leaky(d[nt][3] + bb1);
                    *(float2*)(h3 + g * AST + nb) = r0;
                    *(float2*)(h3 + (g + 8) * AST + nb) = r1;
                }
            }
            __syncthreads();
        }

        // ---- L3: 48 dots x 8 partials of 64 over h3[row][k], dual accumulator ----
        if (tid < 384) {
            const int o = tid >> 3, q = tid & 7;
            const int n = o / 3, c = o - n * 3;
            const float* hp = h3 + n * AST + q * 64;
            const float* wp = W3 + (q * 64) * 6 + c;
            float s0 = 0.f, s1 = 0.f;
#pragma unroll 8
            for (int k = 0; k < 64; k += 2) {
                s0 = fmaf(hp[k], wp[k * 6], s0);
                s1 = fmaf(hp[k + 1], wp[(k + 1) * 6], s1);
            }
            S.part[o][q] = s0 + s1;
        }
        __syncthreads();
        if (tid < 48) {
            const int n = tid / 3, c = tid - n * 3;
            const float* pp = S.part[tid];
            S.fn[n][c] = (((pp[0] + pp[1]) + (pp[2] + pp[3])) +
                          ((pp[4] + pp[5]) + (pp[6] + pp[7]))) + b3v[c];
        }
        __syncthreads();

        // ---- forces + RK4 + outputs + next-step input build ----
        if (tid < BT) {
            const int n = tid;
            const size_t bidx = (size_t)blockIdx.x * BT + n;
            const float F0 = S.fn[n][0] - 0.5f;
            const float F1 = S.fn[n][1] * (-0.4f) - 10.0f;
            const float F2 = S.fn[n][2] * 0.2f - 0.1f;
            float* fo = outF + bidx * 6 * steps + t;
            fo[0 * steps] = F0;
            fo[1 * steps] = F1;
            fo[2 * steps] = F2;
            fo[3 * steps] = 0.f;
            fo[4 * steps] = 0.f;
            fo[5 * steps] = 0.f;
            float xx[12];
#pragma unroll
            for (int s = 0; s < 12; s++) xx[s] = S.x[n][s];
            float k1[12], k2[12], k3[12], k4[12], tm[12];
            derivs(xx, F0, F1, F2, ImR, IvR, k1);
#pragma unroll
            for (int s = 0; s < 12; s++) tm[s] = xx[s] + 0.005f * k1[s];
            derivs(tm, F0, F1, F2, ImR, IvR, k2);
#pragma unroll
            for (int s = 0; s < 12; s++) tm[s] = xx[s] + 0.005f * k2[s];
            derivs(tm, F0, F1, F2, ImR, IvR, k3);
#pragma unroll
            for (int s = 0; s < 12; s++) tm[s] = xx[s] + 0.01f * k3[s];
            derivs(tm, F0, F1, F2, ImR, IvR, k4);
            const float w6 = (float)(0.01 / 6.0);
#pragma unroll
            for (int s = 0; s < 12; s++)
                xx[s] += w6 * (k1[s] + 2.f * k2[s] + 2.f * k3[s] + k4[s]);
            float* xo = outX + bidx * 12 * T + (t + 1);
#pragma unroll
            for (int s = 0; s < 12; s++) {
                S.x[n][s] = xx[s];
                xo[(size_t)s * T] = xx[s];
            }
            // build next step's MLP input
            if (t + 1 < steps) {
                S.in[0 * BT + n] = xx[0] * 1.2732395447351628f;
                S.in[1 * BT + n] = xx[1] * 0.5f;
                S.in[2 * BT + n] = xx[2] * 1.2732395447351628f;
                S.in[3 * BT + n] = xx[3] * 0.1f;
                S.in[4 * BT + n] = xx[4] * 0.016666666666666666f;
                S.in[5 * BT + n] = xx[5] * 0.016666666666666666f;
#pragma unroll
                for (int a = 0; a < 4; a++)
                    S.in[(12 + a) * BT + n] = (act[(bidx * 4 + a) * T + (t + 2)] - 1500.0f) / 500.0f;
                // S.in[6..11] stay 0 from init (never overwritten)
            }
        }
        __syncthreads();
    }
}

extern "C" void kernel_launch(void* const* d_in, const int* in_sizes, int n_in,
                              void* d_out, int out_size) {
    // 0: x_t, 1: act_inps, 2: I_mat, 3: seq_len, 4..11: W0,b0,W1,b1,W2,b2,W3,b3
    const float* x_t = (const float*)d_in[0];
    const float* act = (const float*)d_in[1];
    const float* Im  = (const float*)d_in[2];
    const int* seqp  = (const int*)d_in[3];
    const float* W0  = (const float*)d_in[4];
    const float* b0  = (const float*)d_in[5];
    const float* W1  = (const float*)d_in[6];
    const float* b1  = (const float*)d_in[7];
    const float* W2  = (const float*)d_in[8];
    const float* b2  = (const float*)d_in[9];
    const float* W3  = (const float*)d_in[10];
    const float* b3  = (const float*)d_in[11];

    const int Bn = in_sizes[0] / 12;
    const int grid = Bn / BT;

    wm_prep<<<256, 512>>>(W1, W2);
    wm_rollout<<<grid, NTH>>>(x_t, act, Im, W0, b0, b1, b2, W3, b3,
                              seqp, (float*)d_out, Bn);
}

// round 14
// speedup vs baseline: 3.1223x; 1.2025x over previous
#include <cuda_runtime.h>
#include <cuda_fp16.h>
#include <math.h>
#include <stdint.h>

#define NTH 512
#define BT 16
#define HD 512
#define AST 520   // activation row stride in elems (1040B -> conflict-free ldmatrix phases)

typedef unsigned long long ull;

// Fragment-packed fp16 weights (hi part only): uint2 per (layer, warp, kstep, ntile, lane)
// idx = ((l*16 + w)*32 + ks)*128 + nt*32 + lane ; payload = {wh0, wh1}
__device__ __align__(16) uint2 g_wt[2 * 16 * 32 * 4 * 32];

struct Smem {
    __half Ah[BT * AST];   // activations hi: [row][k]
    __half Al[BT * AST];   // lo
    float in[16 * BT];     // L0 input col-major [k][row]
    float x[BT][12];
    float fn[BT][3];
    float part[48][8];
    float Im[9], Iinv[9];
};

__device__ __forceinline__ float leaky(float v) { return v >= 0.f ? v : 0.01f * v; }
__device__ __forceinline__ ull fma2(ull a, ull b, ull c) {
    ull d;
    asm("fma.rn.f32x2 %0, %1, %2, %3;" : "=l"(d) : "l"(a), "l"(b), "l"(c));
    return d;
}
__device__ __forceinline__ ull pack2(float x) {
    ull r;
    asm("mov.b64 %0, {%1, %1};" : "=l"(r) : "f"(x));
    return r;
}
__device__ __forceinline__ float2 unpack2(ull v) {
    float2 f;
    asm("mov.b64 {%0, %1}, %2;" : "=f"(f.x), "=f"(f.y) : "l"(v));
    return f;
}
__device__ __forceinline__ uint32_t s2u(const void* p) {
    uint32_t a;
    asm("{ .reg .u64 t; cvta.to.shared.u64 t, %1; cvt.u32.u64 %0, t; }" : "=r"(a) : "l"(p));
    return a;
}

// mma.m16n8k16 row.col fp16 -> f32 accum (portable HMMA, sm_70+)
__device__ __forceinline__ void mma16816(float d[4], unsigned a0, unsigned a1, unsigned a2,
                                         unsigned a3, unsigned b0, unsigned b1) {
    asm volatile(
        "mma.sync.aligned.m16n8k16.row.col.f32.f16.f16.f32 "
        "{%0,%1,%2,%3}, {%4,%5,%6,%7}, {%8,%9}, {%0,%1,%2,%3};"
        : "+f"(d[0]), "+f"(d[1]), "+f"(d[2]), "+f"(d[3])
        : "r"(a0), "r"(a1), "r"(a2), "r"(a3), "r"(b0), "r"(b1));
}

// ldmatrix x4: loads full m16k16 b16 A-fragment (lane addr = one 16B row)
__device__ __forceinline__ void ldsm4(unsigned& r0, unsigned& r1, unsigned& r2, unsigned& r3,
                                      uint32_t addr) {
    asm volatile("ldmatrix.sync.aligned.m8n8.x4.shared.b16 {%0,%1,%2,%3}, [%4];"
                 : "=r"(r0), "=r"(r1), "=r"(r2), "=r"(r3) : "r"(addr));
}

__device__ __forceinline__ unsigned h16pack(float lo_elem, float hi_elem) {
    unsigned short s0 = __half_as_ushort(__float2half_rn(lo_elem));
    unsigned short s1 = __half_as_ushort(__float2half_rn(hi_elem));
    return ((unsigned)s1 << 16) | s0;
}

// ---------------- prep: pack W1/W2 (fp16 hi parts) into fragment order ----------------
extern "C" __global__ void wm_prep(const float* __restrict__ W1, const float* __restrict__ W2) {
    int idx = blockIdx.x * blockDim.x + threadIdx.x;   // 131072 total
    int lane = idx & 31;
    int nt = (idx >> 5) & 3;
    int ks = (idx >> 7) & 31;
    int w = (idx >> 12) & 15;
    int l = idx >> 16;
    int g = lane >> 2, tig = lane & 3;
    int k0 = ks * 16 + tig * 2;
    int n = (w * 4 + nt) * 8 + g;
    const float* W = l ? W2 : W1;
    uint2 o;
    o.x = h16pack(W[(k0 + 0) * 512 + n], W[(k0 + 1) * 512 + n]);
    o.y = h16pack(W[(k0 + 8) * 512 + n], W[(k0 + 9) * 512 + n]);
    g_wt[idx] = o;
}

// Rigid-body derivatives, moments == 0. sincosf-based.
__device__ __forceinline__ void derivs(const float x[12], float F0, float F1, float F2,
                                       const float Im[9], const float Iv[9], float dx[12]) {
    float V0 = x[3], V1 = x[4], V2 = x[5];
    float phi = x[6], th = x[7], ps = x[8];
    float w0 = x[9], w1 = x[10], w2 = x[11];
    float sph, cph, sth, cth, sps, cps;
    sincosf(phi, &sph, &cph);
    sincosf(th, &sth, &cth);
    sincosf(ps, &sps, &cps);
    dx[0] = (cth * cps) * V0 + (sph * sth * cps - cph * sps) * V1 + (cph * sth * cps + sph * sps) * V2;
    dx[1] = (cth * sps) * V0 + (sph * sth * sps + cph * cps) * V1 + (cph * sth * sps - sph * cps) * V2;
    dx[2] = (-sth) * V0 + (sph * cth) * V1 + (cph * cth) * V2;
    dx[3] = F0 / 1.5f - (w1 * V2 - w2 * V1);
    dx[4] = F1 / 1.5f - (w2 * V0 - w0 * V2);
    dx[5] = F2 / 1.5f - (w0 * V1 - w1 * V0);
    float ic = 1.0f / fmaxf(cth, 1e-6f);
    float tth = sth * ic;
    dx[6] = w0 + sph * tth * w1 + cph * tth * w2;
    dx[7] = cph * w1 - sph * w2;
    dx[8] = (sph * ic) * w1 + (cph * ic) * w2;
    float Iw0 = Im[0] * w0 + Im[1] * w1 + Im[2] * w2;
    float Iw1 = Im[3] * w0 + Im[4] * w1 + Im[5] * w2;
    float Iw2 = Im[6] * w0 + Im[7] * w1 + Im[8] * w2;
    float c0 = w1 * Iw2 - w2 * Iw1;
    float c1 = w2 * Iw0 - w0 * Iw2;
    float c2 = w0 * Iw1 - w1 * Iw0;
    dx[9]  = -(Iv[0] * c0 + Iv[1] * c1 + Iv[2] * c2);
    dx[10] = -(Iv[3] * c0 + Iv[4] * c1 + Iv[5] * c2);
    dx[11] = -(Iv[6] * c0 + Iv[7] * c1 + Iv[8] * c2);
}

extern "C" __global__ void __launch_bounds__(NTH)
wm_rollout(const float* __restrict__ x_t, const float* __restrict__ act,
           const float* __restrict__ Imat_g,
           const float* __restrict__ W0, const float* __restrict__ b0v,
           const float* __restrict__ b1v, const float* __restrict__ b2v,
           const float* __restrict__ W3, const float* __restrict__ b3v,
           const int* __restrict__ seqp, float* __restrict__ out, int Bn) {
    __shared__ Smem S;
    const int tid = threadIdx.x;
    const int w = tid >> 5, lane = tid & 31;
    const int g = lane >> 2, tig = lane & 3;

    const int T = seqp[0];
    const int steps = T - 1;
    float* outF = out;
    float* outX = out + (size_t)Bn * 6 * steps;

    if (tid == 0) {
        float a = Imat_g[0], b = Imat_g[1], c = Imat_g[2];
        float d = Imat_g[3], e = Imat_g[4], f = Imat_g[5];
        float gg = Imat_g[6], h = Imat_g[7], i = Imat_g[8];
        float A = e * i - f * h, Bc = -(d * i - f * gg), C = d * h - e * gg;
        float id = 1.0f / (a * A + b * Bc + c * C);
        S.Iinv[0] = A * id;  S.Iinv[1] = (c * h - b * i) * id;   S.Iinv[2] = (b * f - c * e) * id;
        S.Iinv[3] = Bc * id; S.Iinv[4] = (a * i - c * gg) * id;  S.Iinv[5] = (c * d - a * f) * id;
        S.Iinv[6] = C * id;  S.Iinv[7] = (b * gg - a * h) * id;  S.Iinv[8] = (a * e - b * d) * id;
#pragma unroll
        for (int k = 0; k < 9; k++) S.Im[k] = Imat_g[k];
    }
    if (tid < BT) {
        const int n = tid;
        const size_t bidx = (size_t)blockIdx.x * BT + n;
#pragma unroll
        for (int s = 0; s < 12; s++) {
            float v = x_t[bidx * 12 + s];
            S.x[n][s] = v;
            outX[bidx * 12 * T + (size_t)s * T] = v;
        }
        // build L0 input for t=0
        S.in[0 * BT + n] = S.x[n][0] * 1.2732395447351628f;
        S.in[1 * BT + n] = S.x[n][1] * 0.5f;
        S.in[2 * BT + n] = S.x[n][2] * 1.2732395447351628f;
        S.in[3 * BT + n] = S.x[n][3] * 0.1f;
        S.in[4 * BT + n] = S.x[n][4] * 0.016666666666666666f;
        S.in[5 * BT + n] = S.x[n][5] * 0.016666666666666666f;
#pragma unroll
        for (int s = 6; s < 12; s++) S.in[s * BT + n] = 0.f;
#pragma unroll
        for (int a = 0; a < 4; a++)
            S.in[(12 + a) * BT + n] = (act[(bidx * 4 + a) * T + 1] - 1500.0f) / 500.0f;
    }
    __syncthreads();

    float ImR[9], IvR[9];
    if (tid < BT) {
#pragma unroll
        for (int k = 0; k < 9; k++) { ImR[k] = S.Im[k]; IvR[k] = S.Iinv[k]; }
    }

    // ldmatrix lane base addresses: row = lane&15, k offset += (lane>>4)*8
    const uint32_t ahBase = s2u(S.Ah) + (uint32_t)(((lane & 15) * AST + ((lane >> 4) << 3)) * 2);
    const uint32_t alBase = ahBase + BT * AST * 2;
    float* h3 = (float*)S.Ah;   // overlay: 16*520 floats == Ah+Al bytes

    for (int t = 0; t < steps; t++) {
        // ---- L0 scalar: neuron c = tid; write Ah/Al[row][c] ----
        {
            const int c = tid;
            ull acc[8];
#pragma unroll
            for (int p = 0; p < 8; p++) acc[p] = 0ULL;
#pragma unroll
            for (int k = 0; k < 16; k++) {
                ull wk = pack2(W0[k * 512 + c]);
                const ull* a = (const ull*)(S.in + k * BT);
#pragma unroll
                for (int p = 0; p < 8; p++) acc[p] = fma2(a[p], wk, acc[p]);
            }
            const float bias = b0v[c];
#pragma unroll
            for (int p = 0; p < 8; p++) {
                float2 v = unpack2(acc[p]);
                float h0 = leaky(v.x + bias);
                float h1 = leaky(v.y + bias);
                __half hh0 = __float2half_rn(h0);
                __half hh1 = __float2half_rn(h1);
                S.Ah[(2 * p) * AST + c] = hh0;
                S.Ah[(2 * p + 1) * AST + c] = hh1;
                S.Al[(2 * p) * AST + c] = __float2half_rn(h0 - __half2float(hh0));
                S.Al[(2 * p + 1) * AST + c] = __float2half_rn(h1 - __half2float(hh1));
            }
        }
        __syncthreads();

        // ---- two MMA layers ----
#pragma unroll
        for (int la = 0; la < 2; la++) {
            // 8 independent accumulator chains: d0 (Ah*Wh), d1 (Al*Wh)
            float d0[4][4], d1[4][4];
#pragma unroll
            for (int nt = 0; nt < 4; nt++)
#pragma unroll
                for (int q = 0; q < 4; q++) { d0[nt][q] = 0.f; d1[nt][q] = 0.f; }

            const uint2* wbase = g_wt + ((size_t)la * 65536 + w * 4096 + lane);
            // 3-deep W register ring
            uint2 wreg[3][4];
#pragma unroll
            for (int s = 0; s < 3; s++)
#pragma unroll
                for (int nt = 0; nt < 4; nt++) wreg[s][nt] = wbase[s * 128 + nt * 32];

#pragma unroll
            for (int ks = 0; ks < 32; ks++) {
                const int slot = ks % 3;
                unsigned ah0, ah1, ah2, ah3, al0, al1, al2, al3;
                ldsm4(ah0, ah1, ah2, ah3, ahBase + ks * 32);
                ldsm4(al0, al1, al2, al3, alBase + ks * 32);
                // 8 chains, each touched once per ks -> spacing 8 issues
#pragma unroll
                for (int nt = 0; nt < 4; nt++)
                    mma16816(d0[nt], ah0, ah1, ah2, ah3, wreg[slot][nt].x, wreg[slot][nt].y);
#pragma unroll
                for (int nt = 0; nt < 4; nt++)
                    mma16816(d1[nt], al0, al1, al2, al3, wreg[slot][nt].x, wreg[slot][nt].y);
                if (ks + 3 < 32) {
#pragma unroll
                    for (int nt = 0; nt < 4; nt++)
                        wreg[slot][nt] = wbase[(ks + 3) * 128 + nt * 32];
                }
            }
            __syncthreads();   // all A reads done before overwrite

            if (la == 0) {
                // epilogue -> next layer's Ah/Al (rows g, g+8; cols nb, nb+1)
#pragma unroll
                for (int nt = 0; nt < 4; nt++) {
                    const int nb = w * 32 + nt * 8 + tig * 2;
                    const float bb0 = b1v[nb], bb1 = b1v[nb + 1];
                    float h00 = leaky(d0[nt][0] + d1[nt][0] + bb0);
                    float h01 = leaky(d0[nt][1] + d1[nt][1] + bb1);
                    float h10 = leaky(d0[nt][2] + d1[nt][2] + bb0);
                    float h11 = leaky(d0[nt][3] + d1[nt][3] + bb1);
                    __half a00 = __float2half_rn(h00);
                    __half a01 = __float2half_rn(h01);
                    __half a10 = __float2half_rn(h10);
                    __half a11 = __float2half_rn(h11);
                    unsigned* AhW = (unsigned*)S.Ah;
                    unsigned* AlW = (unsigned*)S.Al;
                    AhW[(g * AST + nb) >> 1] =
                        ((unsigned)__half_as_ushort(a01) << 16) | __half_as_ushort(a00);
                    AhW[((g + 8) * AST + nb) >> 1] =
                        ((unsigned)__half_as_ushort(a11) << 16) | __half_as_ushort(a10);
                    AlW[(g * AST + nb) >> 1] =
                        ((unsigned)__half_as_ushort(__float2half_rn(h01 - __half2float(a01))) << 16) |
                        __half_as_ushort(__float2half_rn(h00 - __half2float(a00)));
                    AlW[((g + 8) * AST + nb) >> 1] =
                        ((unsigned)__half_as_ushort(__float2half_rn(h11 - __half2float(a11))) << 16) |
                        __half_as_ushort(__float2half_rn(h10 - __half2float(a10)));
                }
            } else {
                // epilogue -> h3 fp32 [row][n]
#pragma unroll
                for (int nt = 0; nt < 4; nt++) {
                    const int nb = w * 32 + nt * 8 + tig * 2;
                    const float bb0 = b2v[nb], bb1 = b2v[nb + 1];
                    float2 r0, r1;
                    r0.x = leaky(d0[nt][0] + d1[nt][0] + bb0);
                    r0.y = leaky(d0[nt][1] + d1[nt][1] + bb1);
                    r1.x = leaky(d0[nt][2] + d1[nt][2] + bb0);
                    r1.y = leaky(d0[nt][3] + d1[nt][3] + bb1);
                    *(float2*)(h3 + g * AST + nb) = r0;
                    *(float2*)(h3 + (g + 8) * AST + nb) = r1;
                }
            }
            __syncthreads();
        }

        // ---- L3: 48 dots x 8 partials of 64 over h3[row][k], dual accumulator ----
        if (tid < 384) {
            const int o = tid >> 3, q = tid & 7;
            const int n = o / 3, c = o - n * 3;
            const float* hp = h3 + n * AST + q * 64;
            const float* wp = W3 + (q * 64) * 6 + c;
            float s0 = 0.f, s1 = 0.f;
#pragma unroll 8
            for (int k = 0; k < 64; k += 2) {
                s0 = fmaf(hp[k], wp[k * 6], s0);
                s1 = fmaf(hp[k + 1], wp[(k + 1) * 6], s1);
            }
            S.part[o][q] = s0 + s1;
        }
        __syncthreads();
        if (tid < 48) {
            const int n = tid / 3, c = tid - n * 3;
            const float* pp = S.part[tid];
            S.fn[n][c] = (((pp[0] + pp[1]) + (pp[2] + pp[3])) +
                          ((pp[4] + pp[5]) + (pp[6] + pp[7]))) + b3v[c];
        }
        __syncthreads();

        // ---- forces + RK4 + outputs + next-step input build ----
        if (tid < BT) {
            const int n = tid;
            const size_t bidx = (size_t)blockIdx.x * BT + n;
            const float F0 = S.fn[n][0] - 0.5f;
            const float F1 = S.fn[n][1] * (-0.4f) - 10.0f;
            const float F2 = S.fn[n][2] * 0.2f - 0.1f;
            float* fo = outF + bidx * 6 * steps + t;
            fo[0 * steps] = F0;
            fo[1 * steps] = F1;
            fo[2 * steps] = F2;
            fo[3 * steps] = 0.f;
            fo[4 * steps] = 0.f;
            fo[5 * steps] = 0.f;
            float xx[12];
#pragma unroll
            for (int s = 0; s < 12; s++) xx[s] = S.x[n][s];
            float k1[12], k2[12], k3[12], k4[12], tm[12];
            derivs(xx, F0, F1, F2, ImR, IvR, k1);
#pragma unroll
            for (int s = 0; s < 12; s++) tm[s] = xx[s] + 0.005f * k1[s];
            derivs(tm, F0, F1, F2, ImR, IvR, k2);
#pragma unroll
            for (int s = 0; s < 12; s++) tm[s] = xx[s] + 0.005f * k2[s];
            derivs(tm, F0, F1, F2, ImR, IvR, k3);
#pragma unroll
            for (int s = 0; s < 12; s++) tm[s] = xx[s] + 0.01f * k3[s];
            derivs(tm, F0, F1, F2, ImR, IvR, k4);
            const float w6 = (float)(0.01 / 6.0);
#pragma unroll
            for (int s = 0; s < 12; s++)
                xx[s] += w6 * (k1[s] + 2.f * k2[s] + 2.f * k3[s] + k4[s]);
            float* xo = outX + bidx * 12 * T + (t + 1);
#pragma unroll
            for (int s = 0; s < 12; s++) {
                S.x[n][s] = xx[s];
                xo[(size_t)s * T] = xx[s];
            }
            // build next step's MLP input
            if (t + 1 < steps) {
                S.in[0 * BT + n] = xx[0] * 1.2732395447351628f;
                S.in[1 * BT + n] = xx[1] * 0.5f;
                S.in[2 * BT + n] = xx[2] * 1.2732395447351628f;
                S.in[3 * BT + n] = xx[3] * 0.1f;
                S.in[4 * BT + n] = xx[4] * 0.016666666666666666f;
                S.in[5 * BT + n] = xx[5] * 0.016666666666666666f;
#pragma unroll
                for (int a = 0; a < 4; a++)
                    S.in[(12 + a) * BT + n] = (act[(bidx * 4 + a) * T + (t + 2)] - 1500.0f) / 500.0f;
                // S.in[6..11] stay 0 from init (never overwritten)
            }
        }
        __syncthreads();
    }
}

extern "C" void kernel_launch(void* const* d_in, const int* in_sizes, int n_in,
                              void* d_out, int out_size) {
    // 0: x_t, 1: act_inps, 2: I_mat, 3: seq_len, 4..11: W0,b0,W1,b1,W2,b2,W3,b3
    const float* x_t = (const float*)d_in[0];
    const float* act = (const float*)d_in[1];
    const float* Im  = (const float*)d_in[2];
    const int* seqp  = (const int*)d_in[3];
    const float* W0  = (const float*)d_in[4];
    const float* b0  = (const float*)d_in[5];
    const float* W1  = (const float*)d_in[6];
    const float* b1  = (const float*)d_in[7];
    const float* W2  = (const float*)d_in[8];
    const float* b2  = (const float*)d_in[9];
    const float* W3  = (const float*)d_in[10];
    const float* b3  = (const float*)d_in[11];

    const int Bn = in_sizes[0] / 12;
    const int grid = Bn / BT;

    wm_prep<<<256, 512>>>(W1, W2);
    wm_rollout<<<grid, NTH>>>(x_t, act, Im, W0, b0, b1, b2, W3, b3,
                              seqp, (float*)d_out, Bn);
}

// round 15
// speedup vs baseline: 3.1911x; 1.0221x over previous
#include <cuda_runtime.h>
#include <cuda_fp16.h>
#include <math.h>
#include <stdint.h>

#define NTH 512
#define BT 16
#define HD 512
#define AST 520   // activation row stride in elems (1040B = 65*16B -> ldmatrix-aligned, conflict-free)

typedef unsigned long long ull;

// Fragment-packed fp16 weights (hi part only): uint2 per (layer, warp, kstep, ntile, lane)
__device__ __align__(16) uint2 g_wt[2 * 16 * 32 * 4 * 32];

struct Smem {
    __half Ah[BT * AST];   // activations hi: [row][k]
    __half Al[BT * AST];   // lo
    float W0s[16 * 512];   // W0 staged
    float W3s[512 * 3];    // W3 cols 0..2 staged
    float b0s[512], b1s[512], b2s[512];
    float in[16 * BT];     // L0 input col-major [k][row]
    float x[BT][12];
    float fn[BT][3];
    float Im[9], Iinv[9], b3s[3];
};

__device__ __forceinline__ float leaky(float v) { return v >= 0.f ? v : 0.01f * v; }
__device__ __forceinline__ ull fma2(ull a, ull b, ull c) {
    ull d;
    asm("fma.rn.f32x2 %0, %1, %2, %3;" : "=l"(d) : "l"(a), "l"(b), "l"(c));
    return d;
}
__device__ __forceinline__ ull pack2(float x) {
    ull r;
    asm("mov.b64 %0, {%1, %1};" : "=l"(r) : "f"(x));
    return r;
}
__device__ __forceinline__ float2 unpack2(ull v) {
    float2 f;
    asm("mov.b64 {%0, %1}, %2;" : "=f"(f.x), "=f"(f.y) : "l"(v));
    return f;
}
__device__ __forceinline__ uint32_t s2u(const void* p) {
    uint32_t a;
    asm("{ .reg .u64 t; cvta.to.shared.u64 t, %1; cvt.u32.u64 %0, t; }" : "=r"(a) : "l"(p));
    return a;
}

// mma.m16n8k16 row.col fp16 -> f32 accum
__device__ __forceinline__ void mma16816(float d[4], unsigned a0, unsigned a1, unsigned a2,
                                         unsigned a3, unsigned b0, unsigned b1) {
    asm volatile(
        "mma.sync.aligned.m16n8k16.row.col.f32.f16.f16.f32 "
        "{%0,%1,%2,%3}, {%4,%5,%6,%7}, {%8,%9}, {%0,%1,%2,%3};"
        : "+f"(d[0]), "+f"(d[1]), "+f"(d[2]), "+f"(d[3])
        : "r"(a0), "r"(a1), "r"(a2), "r"(a3), "r"(b0), "r"(b1));
}
__device__ __forceinline__ void ldsm4(unsigned& r0, unsigned& r1, unsigned& r2, unsigned& r3,
                                      uint32_t addr) {
    asm volatile("ldmatrix.sync.aligned.m8n8.x4.shared.b16 {%0,%1,%2,%3}, [%4];"
                 : "=r"(r0), "=r"(r1), "=r"(r2), "=r"(r3) : "r"(addr));
}
__device__ __forceinline__ unsigned h16pack(float lo_elem, float hi_elem) {
    unsigned short s0 = __half_as_ushort(__float2half_rn(lo_elem));
    unsigned short s1 = __half_as_ushort(__float2half_rn(hi_elem));
    return ((unsigned)s1 << 16) | s0;
}

// ---------------- prep: pack W1/W2 (fp16 hi parts) into fragment order ----------------
extern "C" __global__ void wm_prep(const float* __restrict__ W1, const float* __restrict__ W2) {
    int idx = blockIdx.x * blockDim.x + threadIdx.x;   // 131072 total
    int lane = idx & 31;
    int nt = (idx >> 5) & 3;
    int ks = (idx >> 7) & 31;
    int w = (idx >> 12) & 15;
    int l = idx >> 16;
    int g = lane >> 2, tig = lane & 3;
    int k0 = ks * 16 + tig * 2;
    int n = (w * 4 + nt) * 8 + g;
    const float* W = l ? W2 : W1;
    uint2 o;
    o.x = h16pack(W[(k0 + 0) * 512 + n], W[(k0 + 1) * 512 + n]);
    o.y = h16pack(W[(k0 + 8) * 512 + n], W[(k0 + 9) * 512 + n]);
    g_wt[idx] = o;
}

// Rigid-body derivatives, moments == 0. sincosf-based.
__device__ __forceinline__ void derivs(const float x[12], float F0, float F1, float F2,
                                       const float Im[9], const float Iv[9], float dx[12]) {
    float V0 = x[3], V1 = x[4], V2 = x[5];
    float phi = x[6], th = x[7], ps = x[8];
    float w0 = x[9], w1 = x[10], w2 = x[11];
    float sph, cph, sth, cth, sps, cps;
    sincosf(phi, &sph, &cph);
    sincosf(th, &sth, &cth);
    sincosf(ps, &sps, &cps);
    dx[0] = (cth * cps) * V0 + (sph * sth * cps - cph * sps) * V1 + (cph * sth * cps + sph * sps) * V2;
    dx[1] = (cth * sps) * V0 + (sph * sth * sps + cph * cps) * V1 + (cph * sth * sps - sph * cps) * V2;
    dx[2] = (-sth) * V0 + (sph * cth) * V1 + (cph * cth) * V2;
    dx[3] = F0 / 1.5f - (w1 * V2 - w2 * V1);
    dx[4] = F1 / 1.5f - (w2 * V0 - w0 * V2);
    dx[5] = F2 / 1.5f - (w0 * V1 - w1 * V0);
    float ic = 1.0f / fmaxf(cth, 1e-6f);
    float tth = sth * ic;
    dx[6] = w0 + sph * tth * w1 + cph * tth * w2;
    dx[7] = cph * w1 - sph * w2;
    dx[8] = (sph * ic) * w1 + (cph * ic) * w2;
    float Iw0 = Im[0] * w0 + Im[1] * w1 + Im[2] * w2;
    float Iw1 = Im[3] * w0 + Im[4] * w1 + Im[5] * w2;
    float Iw2 = Im[6] * w0 + Im[7] * w1 + Im[8] * w2;
    float c0 = w1 * Iw2 - w2 * Iw1;
    float c1 = w2 * Iw0 - w0 * Iw2;
    float c2 = w0 * Iw1 - w1 * Iw0;
    dx[9]  = -(Iv[0] * c0 + Iv[1] * c1 + Iv[2] * c2);
    dx[10] = -(Iv[3] * c0 + Iv[4] * c1 + Iv[5] * c2);
    dx[11] = -(Iv[6] * c0 + Iv[7] * c1 + Iv[8] * c2);
}

extern "C" __global__ void __launch_bounds__(NTH)
wm_rollout(const float* __restrict__ x_t, const float* __restrict__ act,
           const float* __restrict__ Imat_g,
           const float* __restrict__ W0, const float* __restrict__ b0v,
           const float* __restrict__ b1v, const float* __restrict__ b2v,
           const float* __restrict__ W3, const float* __restrict__ b3v,
           const int* __restrict__ seqp, float* __restrict__ out, int Bn) {
    extern __shared__ char raw[];
    Smem& S = *reinterpret_cast<Smem*>(raw);
    const int tid = threadIdx.x;
    const int w = tid >> 5, lane = tid & 31;
    const int g = lane >> 2, tig = lane & 3;

    const int T = seqp[0];
    const int steps = T - 1;
    float* outF = out;
    float* outX = out + (size_t)Bn * 6 * steps;

    // ---- stage weights/biases into smem ----
    for (int i = tid; i < 16 * 512; i += NTH) S.W0s[i] = W0[i];
    for (int i = tid; i < 512 * 3; i += NTH) {
        int k = i / 3, c = i - k * 3;
        S.W3s[i] = W3[k * 6 + c];
    }
    for (int i = tid; i < 512; i += NTH) {
        S.b0s[i] = b0v[i];
        S.b1s[i] = b1v[i];
        S.b2s[i] = b2v[i];
    }
    if (tid < 3) S.b3s[tid] = b3v[tid];

    if (tid == 0) {
        float a = Imat_g[0], b = Imat_g[1], c = Imat_g[2];
        float d = Imat_g[3], e = Imat_g[4], f = Imat_g[5];
        float gg = Imat_g[6], h = Imat_g[7], i = Imat_g[8];
        float A = e * i - f * h, Bc = -(d * i - f * gg), C = d * h - e * gg;
        float id = 1.0f / (a * A + b * Bc + c * C);
        S.Iinv[0] = A * id;  S.Iinv[1] = (c * h - b * i) * id;   S.Iinv[2] = (b * f - c * e) * id;
        S.Iinv[3] = Bc * id; S.Iinv[4] = (a * i - c * gg) * id;  S.Iinv[5] = (c * d - a * f) * id;
        S.Iinv[6] = C * id;  S.Iinv[7] = (b * gg - a * h) * id;  S.Iinv[8] = (a * e - b * d) * id;
#pragma unroll
        for (int k = 0; k < 9; k++) S.Im[k] = Imat_g[k];
    }
    if (tid < BT) {
        const int n = tid;
        const size_t bidx = (size_t)blockIdx.x * BT + n;
#pragma unroll
        for (int s = 0; s < 12; s++) {
            float v = x_t[bidx * 12 + s];
            S.x[n][s] = v;
            outX[bidx * 12 * T + (size_t)s * T] = v;
        }
        // build L0 input for t=0
        S.in[0 * BT + n] = S.x[n][0] * 1.2732395447351628f;
        S.in[1 * BT + n] = S.x[n][1] * 0.5f;
        S.in[2 * BT + n] = S.x[n][2] * 1.2732395447351628f;
        S.in[3 * BT + n] = S.x[n][3] * 0.1f;
        S.in[4 * BT + n] = S.x[n][4] * 0.016666666666666666f;
        S.in[5 * BT + n] = S.x[n][5] * 0.016666666666666666f;
#pragma unroll
        for (int s = 6; s < 12; s++) S.in[s * BT + n] = 0.f;
#pragma unroll
        for (int a = 0; a < 4; a++)
            S.in[(12 + a) * BT + n] = (act[(bidx * 4 + a) * T + 1] - 1500.0f) / 500.0f;
    }
    __syncthreads();

    float ImR[9], IvR[9];
    if (tid < BT) {
#pragma unroll
        for (int k = 0; k < 9; k++) { ImR[k] = S.Im[k]; IvR[k] = S.Iinv[k]; }
    }

    // ldmatrix lane base addresses: row = lane&15, k offset += (lane>>4)*8
    const uint32_t ahBase = s2u(S.Ah) + (uint32_t)(((lane & 15) * AST + ((lane >> 4) << 3)) * 2);
    const uint32_t alBase = ahBase + BT * AST * 2;
    float* h3 = (float*)S.Ah;   // overlay: 16*520 floats == Ah+Al bytes

    for (int t = 0; t < steps; t++) {
        // ---- L0 scalar (weights from smem): neuron c = tid ----
        {
            const int c = tid;
            ull acc[8];
#pragma unroll
            for (int p = 0; p < 8; p++) acc[p] = 0ULL;
#pragma unroll
            for (int k = 0; k < 16; k++) {
                ull wk = pack2(S.W0s[k * 512 + c]);
                const ull* a = (const ull*)(S.in + k * BT);
#pragma unroll
                for (int p = 0; p < 8; p++) acc[p] = fma2(a[p], wk, acc[p]);
            }
            const float bias = S.b0s[c];
#pragma unroll
            for (int p = 0; p < 8; p++) {
                float2 v = unpack2(acc[p]);
                float h0 = leaky(v.x + bias);
                float h1 = leaky(v.y + bias);
                __half hh0 = __float2half_rn(h0);
                __half hh1 = __float2half_rn(h1);
                S.Ah[(2 * p) * AST + c] = hh0;
                S.Ah[(2 * p + 1) * AST + c] = hh1;
                S.Al[(2 * p) * AST + c] = __float2half_rn(h0 - __half2float(hh0));
                S.Al[(2 * p + 1) * AST + c] = __float2half_rn(h1 - __half2float(hh1));
            }
        }
        __syncthreads();

        // ---- two MMA layers ----
#pragma unroll
        for (int la = 0; la < 2; la++) {
            float d0[4][4], d1[4][4];
#pragma unroll
            for (int nt = 0; nt < 4; nt++)
#pragma unroll
                for (int q = 0; q < 4; q++) { d0[nt][q] = 0.f; d1[nt][q] = 0.f; }

            const uint2* wbase = g_wt + ((size_t)la * 65536 + w * 4096 + lane);
            uint2 wreg[3][4];
#pragma unroll
            for (int s = 0; s < 3; s++)
#pragma unroll
                for (int nt = 0; nt < 4; nt++) wreg[s][nt] = wbase[s * 128 + nt * 32];

            // A-fragment pipeline: load ks=0 ahead
            unsigned ah[4], al[4], ahn[4], aln[4];
            ldsm4(ah[0], ah[1], ah[2], ah[3], ahBase);
            ldsm4(al[0], al[1], al[2], al[3], alBase);

#pragma unroll
            for (int ks = 0; ks < 32; ks++) {
                const int slot = ks % 3;
                // prefetch next A fragments before consuming current
                if (ks + 1 < 32) {
                    ldsm4(ahn[0], ahn[1], ahn[2], ahn[3], ahBase + (ks + 1) * 32);
                    ldsm4(aln[0], aln[1], aln[2], aln[3], alBase + (ks + 1) * 32);
                }
                // prefetch W for ks+3
                if (ks + 3 < 32) {
#pragma unroll
                    for (int nt = 0; nt < 4; nt++)
                        wreg[slot == 0 ? 0 : slot][nt] = wreg[slot][nt];   // no-op keep
                }
#pragma unroll
                for (int nt = 0; nt < 4; nt++)
                    mma16816(d0[nt], ah[0], ah[1], ah[2], ah[3], wreg[slot][nt].x, wreg[slot][nt].y);
#pragma unroll
                for (int nt = 0; nt < 4; nt++)
                    mma16816(d1[nt], al[0], al[1], al[2], al[3], wreg[slot][nt].x, wreg[slot][nt].y);
                if (ks + 3 < 32) {
#pragma unroll
                    for (int nt = 0; nt < 4; nt++)
                        wreg[slot][nt] = wbase[(ks + 3) * 128 + nt * 32];
                }
#pragma unroll
                for (int q = 0; q < 4; q++) { ah[q] = ahn[q]; al[q] = aln[q]; }
            }
            __syncthreads();   // all A reads done before overwrite

            if (la == 0) {
#pragma unroll
                for (int nt = 0; nt < 4; nt++) {
                    const int nb = w * 32 + nt * 8 + tig * 2;
                    const float bb0 = S.b1s[nb], bb1 = S.b1s[nb + 1];
                    float h00 = leaky(d0[nt][0] + d1[nt][0] + bb0);
                    float h01 = leaky(d0[nt][1] + d1[nt][1] + bb1);
                    float h10 = leaky(d0[nt][2] + d1[nt][2] + bb0);
                    float h11 = leaky(d0[nt][3] + d1[nt][3] + bb1);
                    __half a00 = __float2half_rn(h00);
                    __half a01 = __float2half_rn(h01);
                    __half a10 = __float2half_rn(h10);
                    __half a11 = __float2half_rn(h11);
                    unsigned* AhW = (unsigned*)S.Ah;
                    unsigned* AlW = (unsigned*)S.Al;
                    AhW[(g * AST + nb) >> 1] =
                        ((unsigned)__half_as_ushort(a01) << 16) | __half_as_ushort(a00);
                    AhW[((g + 8) * AST + nb) >> 1] =
                        ((unsigned)__half_as_ushort(a11) << 16) | __half_as_ushort(a10);
                    AlW[(g * AST + nb) >> 1] =
                        ((unsigned)__half_as_ushort(__float2half_rn(h01 - __half2float(a01))) << 16) |
                        __half_as_ushort(__float2half_rn(h00 - __half2float(a00)));
                    AlW[((g + 8) * AST + nb) >> 1] =
                        ((unsigned)__half_as_ushort(__float2half_rn(h11 - __half2float(a11))) << 16) |
                        __half_as_ushort(__float2half_rn(h10 - __half2float(a10)));
                }
            } else {
#pragma unroll
                for (int nt = 0; nt < 4; nt++) {
                    const int nb = w * 32 + nt * 8 + tig * 2;
                    const float bb0 = S.b2s[nb], bb1 = S.b2s[nb + 1];
                    float2 r0, r1;
                    r0.x = leaky(d0[nt][0] + d1[nt][0] + bb0);
                    r0.y = leaky(d0[nt][1] + d1[nt][1] + bb1);
                    r1.x = leaky(d0[nt][2] + d1[nt][2] + bb0);
                    r1.y = leaky(d0[nt][3] + d1[nt][3] + bb1);
                    *(float2*)(h3 + g * AST + nb) = r0;
                    *(float2*)(h3 + (g + 8) * AST + nb) = r1;
                }
            }
            __syncthreads();
        }

        // ---- L3 (weights from smem) + warp shuffle reduce ----
        if (tid < 384) {
            const int o = tid >> 3, q = tid & 7;
            const int n = o / 3, c = o - n * 3;
            const float* hp = h3 + n * AST + q * 64;
            float s0 = 0.f, s1 = 0.f;
            const int kb = q * 64;
#pragma unroll 8
            for (int k = 0; k < 64; k += 2) {
                s0 = fmaf(hp[k], S.W3s[(kb + k) * 3 + c], s0);
                s1 = fmaf(hp[k + 1], S.W3s[(kb + k + 1) * 3 + c], s1);
            }
            float s = s0 + s1;
#pragma unroll
            for (int dsh = 4; dsh >= 1; dsh >>= 1)
                s += __shfl_xor_sync(0xffffffffu, s, dsh);
            if (q == 0) S.fn[n][c] = s + S.b3s[c];
        }
        __syncthreads();

        // ---- forces + RK4 + outputs + next-step input build ----
        if (tid < BT) {
            const int n = tid;
            const size_t bidx = (size_t)blockIdx.x * BT + n;
            const float F0 = S.fn[n][0] - 0.5f;
            const float F1 = S.fn[n][1] * (-0.4f) - 10.0f;
            const float F2 = S.fn[n][2] * 0.2f - 0.1f;
            float* fo = outF + bidx * 6 * steps + t;
            fo[0 * steps] = F0;
            fo[1 * steps] = F1;
            fo[2 * steps] = F2;
            fo[3 * steps] = 0.f;
            fo[4 * steps] = 0.f;
            fo[5 * steps] = 0.f;
            float xx[12];
#pragma unroll
            for (int s = 0; s < 12; s++) xx[s] = S.x[n][s];
            float k1[12], k2[12], k3[12], k4[12], tm[12];
            derivs(xx, F0, F1, F2, ImR, IvR, k1);
#pragma unroll
            for (int s = 0; s < 12; s++) tm[s] = xx[s] + 0.005f * k1[s];
            derivs(tm, F0, F1, F2, ImR, IvR, k2);
#pragma unroll
            for (int s = 0; s < 12; s++) tm[s] = xx[s] + 0.005f * k2[s];
            derivs(tm, F0, F1, F2, ImR, IvR, k3);
#pragma unroll
            for (int s = 0; s < 12; s++) tm[s] = xx[s] + 0.01f * k3[s];
            derivs(tm, F0, F1, F2, ImR, IvR, k4);
            const float w6 = (float)(0.01 / 6.0);
#pragma unroll
            for (int s = 0; s < 12; s++)
                xx[s] += w6 * (k1[s] + 2.f * k2[s] + 2.f * k3[s] + k4[s]);
            float* xo = outX + bidx * 12 * T + (t + 1);
#pragma unroll
            for (int s = 0; s < 12; s++) {
                S.x[n][s] = xx[s];
                xo[(size_t)s * T] = xx[s];
            }
            if (t + 1 < steps) {
                S.in[0 * BT + n] = xx[0] * 1.2732395447351628f;
                S.in[1 * BT + n] = xx[1] * 0.5f;
                S.in[2 * BT + n] = xx[2] * 1.2732395447351628f;
                S.in[3 * BT + n] = xx[3] * 0.1f;
                S.in[4 * BT + n] = xx[4] * 0.016666666666666666f;
                S.in[5 * BT + n] = xx[5] * 0.016666666666666666f;
#pragma unroll
                for (int a = 0; a < 4; a++)
                    S.in[(12 + a) * BT + n] = (act[(bidx * 4 + a) * T + (t + 2)] - 1500.0f) / 500.0f;
            }
        }
        __syncthreads();
    }
}

extern "C" void kernel_launch(void* const* d_in, const int* in_sizes, int n_in,
                              void* d_out, int out_size) {
    // 0: x_t, 1: act_inps, 2: I_mat, 3: seq_len, 4..11: W0,b0,W1,b1,W2,b2,W3,b3
    const float* x_t = (const float*)d_in[0];
    const float* act = (const float*)d_in[1];
    const float* Im  = (const float*)d_in[2];
    const int* seqp  = (const int*)d_in[3];
    const float* W0  = (const float*)d_in[4];
    const float* b0  = (const float*)d_in[5];
    const float* W1  = (const float*)d_in[6];
    const float* b1  = (const float*)d_in[7];
    const float* W2  = (const float*)d_in[8];
    const float* b2  = (const float*)d_in[9];
    const float* W3  = (const float*)d_in[10];
    const float* b3  = (const float*)d_in[11];

    const int Bn = in_sizes[0] / 12;
    const int grid = Bn / BT;
    const size_t sm = sizeof(Smem);

    wm_prep<<<256, 512>>>(W1, W2);
    cudaFuncSetAttribute(wm_rollout, cudaFuncAttributeMaxDynamicSharedMemorySize, (int)sm);
    wm_rollout<<<grid, NTH, sm>>>(x_t, act, Im, W0, b0, b1, b2, W3, b3,
                                  seqp, (float*)d_out, Bn);
}